// round 5
// baseline (speedup 1.0000x reference)
#include <cuda_runtime.h>
#include <cuda_bf16.h>
#include <math.h>

// Problem constants
#define BATCH 8
#define CIN   32
#define CMID  16
#define COUT  32
#define HH    384
#define WW    384
#define PLANE (HH*WW)            // 147456
#define NPLANES (BATCH*CIN)      // 256
#define NTAPS 25
#define NSLICE 8                 // row-slices per plane for stats
#define SLICE_ROWS 48
#define SLICE_F4 (SLICE_ROWS*WW/4)   // 4608 float4 per slice

typedef unsigned long long ull;

// packed f32x2 helpers
#define FFMA2(acc, a, b) asm("fma.rn.f32x2 %0, %1, %2, %0;" : "+l"(acc) : "l"(a), "l"(b))
#define PACKF2(out, lo, hi) asm("mov.b64 %0, {%1, %2};" : "=l"(out) : "f"(lo), "f"(hi))
#define UNPACKF2(lo, hi, in) asm("mov.b64 {%0, %1}, %2;" : "=f"(lo), "=f"(hi) : "l"(in))

// ---- scratch (device globals; no allocation allowed) ----
__device__ float g_part[NPLANES * NSLICE * 13];  // per (plane,slice) partial stats
__device__ float g_W25[CIN * NTAPS * CMID];      // folded stage-1 conv weights [ci][tap][c]
__device__ float g_M[BATCH * COUT * CMID];       // per-batch pointwise weights
__device__ float g_beta[BATCH * COUT];           // per-batch bias

// ============================================================
// Kernel A: per-slice stats. grid = 2048 blocks (plane*8+slice), 256 threads.
// st layout: [0]=T, [1..3]=rowsum 0..2, [4..6]=rowsum 381..383,
//            [7..9]=colsum 0..2, [10..12]=colsum 381..383
// ============================================================
__device__ __forceinline__ float warp_red(float v) {
#pragma unroll
    for (int o = 16; o > 0; o >>= 1) v += __shfl_xor_sync(0xffffffffu, v, o);
    return v;
}

__global__ void stats_kernel(const float* __restrict__ x) {
    int blk = blockIdx.x;
    int plane = blk >> 3, slice = blk & 7;
    const float4* xp = (const float4*)(x + (size_t)plane * PLANE + (size_t)slice * SLICE_ROWS * WW);
    int tid = threadIdx.x;
    const bool bnd = (slice == 0 || slice == 7);

    float T = 0.f, c0 = 0.f, c1 = 0.f, c2 = 0.f, c3 = 0.f, c4 = 0.f, c5 = 0.f;
    float r0 = 0.f, r1 = 0.f, r2 = 0.f;

#pragma unroll
    for (int it = 0; it < SLICE_F4 / 256; ++it) {
        int i = tid + it * 256;
        float4 v = xp[i];
        float s4 = v.x + v.y + v.z + v.w;
        T += s4;
        int cq = i % 96;
        if (cq == 0)  { c0 += v.x; c1 += v.y; c2 += v.z; }
        if (cq == 95) { c3 += v.y; c4 += v.z; c5 += v.w; }
        if (bnd) {
            int lr = i / 96;                 // local row 0..47
            int key = (slice == 0) ? lr : (47 - lr);   // 0,1,2 are boundary rows
            if (key == 0) r0 += s4;          // row 0 / row 383
            else if (key == 1) r1 += s4;     // row 1 / row 382
            else if (key == 2) r2 += s4;     // row 2 / row 381
        }
    }

    __shared__ float s13[13];
    if (tid < 13) s13[tid] = 0.f;
    __syncthreads();

    T = warp_red(T);
    c0 = warp_red(c0); c1 = warp_red(c1); c2 = warp_red(c2);
    c3 = warp_red(c3); c4 = warp_red(c4); c5 = warp_red(c5);
    if (bnd) { r0 = warp_red(r0); r1 = warp_red(r1); r2 = warp_red(r2); }

    if ((tid & 31) == 0) {
        atomicAdd(&s13[0], T);
        atomicAdd(&s13[7], c0);  atomicAdd(&s13[8], c1);  atomicAdd(&s13[9], c2);
        atomicAdd(&s13[10], c3); atomicAdd(&s13[11], c4); atomicAdd(&s13[12], c5);
        if (bnd) {
            if (slice == 0) {            // rows 0,1,2 -> st[1],st[2],st[3]
                atomicAdd(&s13[1], r0); atomicAdd(&s13[2], r1); atomicAdd(&s13[3], r2);
            } else {                     // key0=row383->st[6], key1=row382->st[5], key2=row381->st[4]
                atomicAdd(&s13[6], r0); atomicAdd(&s13[5], r1); atomicAdd(&s13[4], r2);
            }
        }
    }
    __syncthreads();
    if (tid < 13) g_part[blk * 13 + tid] = s13[tid];
}

// partial sum of x over the valid shifted region for offset (dy,dx), exact borders
__device__ __forceinline__ float ps_fun(const float* __restrict__ xp,
                                        const float* __restrict__ st,
                                        int dy, int dx) {
    float s = st[0];
    if (dy > 0)      { for (int r = 0; r <  dy; ++r) s -= st[1 + r]; }
    else if (dy < 0) { for (int r = 0; r < -dy; ++r) s -= st[6 - r]; }
    if (dx > 0)      { for (int c = 0; c <  dx; ++c) s -= st[7 + c]; }
    else if (dx < 0) { for (int c = 0; c < -dx; ++c) s -= st[12 - c]; }
    if (dy != 0 && dx != 0) {
        int r0 = (dy > 0) ? 0 : HH + dy;
        int r1 = (dy > 0) ? dy - 1 : HH - 1;
        int c0 = (dx > 0) ? 0 : WW + dx;
        int c1 = (dx > 0) ? dx - 1 : WW - 1;
        for (int r = r0; r <= r1; ++r)
            for (int c = c0; c <= c1; ++c)
                s += xp[r * WW + c];  // add back doubly-subtracted corner
    }
    return s;
}

// ============================================================
// Kernel B: fold everything into W25 / M / beta. 1 block, 256 threads.
// ============================================================
__global__ void prep_kernel(const float* __restrict__ x,
                            const float* __restrict__ w1, const float* __restrict__ b1,
                            const float* __restrict__ w2, const float* __restrict__ b2,
                            const float* __restrict__ w3, const float* __restrict__ b3,
                            const float* __restrict__ w4, const float* __restrict__ b4,
                            const float* __restrict__ w5, const float* __restrict__ b5,
                            const float* __restrict__ gcn_w, const float* __restrict__ gcn_b,
                            const float* __restrict__ attn,
                            const float* __restrict__ fusion_w, const float* __restrict__ fusion_b) {
    __shared__ float nf[BATCH][5][CMID];   // branch node-feats WITHOUT biases
    __shared__ float zsh[BATCH][CMID];
    __shared__ float fnsh[BATCH][CMID];
    __shared__ float swsh[5];
    int tid = threadIdx.x;

    for (int i = tid; i < BATCH * 5 * CMID; i += 256) ((float*)nf)[i] = 0.f;
    if (tid == 0) {
        float m = attn[0];
        for (int i = 1; i < 5; ++i) m = fmaxf(m, attn[i]);
        float e[5], s = 0.f;
        for (int i = 0; i < 5; ++i) { e[i] = expf(attn[i] - m); s += e[i]; }
        for (int i = 0; i < 5; ++i) swsh[i] = e[i] / s;
    }
    __syncthreads();

    // ---- phase 1: exact per-branch node features (means with zero-padding) ----
    {
        int b = tid >> 5, ci = tid & 31;
        int plane = b * CIN + ci;
        const float* xp = x + (size_t)plane * PLANE;
        float st[13];
        for (int i = 0; i < 13; ++i) {
            float s = 0.f;
            for (int sl = 0; sl < NSLICE; ++sl) s += g_part[(plane * NSLICE + sl) * 13 + i];
            st[i] = s;
        }
        const float invHW = 1.0f / (float)PLANE;
        float xm = st[0] * invHW;
        for (int c = 0; c < CMID; ++c) {
            atomicAdd(&nf[b][0][c], w1[c * CIN + ci] * xm);   // f1: 1x1
            atomicAdd(&nf[b][4][c], w5[c * CIN + ci] * xm);   // f5: 1x1 on GAP
        }
        for (int d = 1; d <= 3; ++d) {
            float ps[9];
            for (int ky = 0; ky < 3; ++ky)
                for (int kx = 0; kx < 3; ++kx)
                    ps[ky * 3 + kx] = ps_fun(xp, st, d * (ky - 1), d * (kx - 1)) * invHW;
            const float* wd = (d == 1) ? w2 : (d == 2) ? w3 : w4;
            for (int c = 0; c < CMID; ++c) {
                float p = 0.f;
                for (int j = 0; j < 9; ++j) p += wd[(c * CIN + ci) * 9 + j] * ps[j];
                atomicAdd(&nf[b][d][c], p);
            }
        }
    }
    __syncthreads();

    // ---- phase 2: z = mean over branches (A_hat uniform) incl. biases ----
    if (tid < BATCH * CMID) {
        int b = tid >> 4, c = tid & 15;
        float s = nf[b][0][c] + nf[b][1][c] + nf[b][2][c] + nf[b][3][c] + nf[b][4][c]
                + b1[c] + b2[c] + b3[c] + b4[c] + b5[c];
        zsh[b][c] = 0.2f * s;
    }
    __syncthreads();

    // ---- phase 3: fn = z @ gcn_w + gcn_b ----
    if (tid < BATCH * CMID) {
        int b = tid >> 4, c = tid & 15;
        float s = gcn_b[c];
        for (int k = 0; k < CMID; ++k) s += zsh[b][k] * gcn_w[k * CMID + c];
        fnsh[b][c] = s;
    }
    __syncthreads();

    // ---- phase 4: M, beta ----
    {
        int b = tid >> 5, co = tid & 31;
        float bt = fusion_b[co];
        for (int c = 0; c < CMID; ++c) {
            float K = swsh[0] * b1[c] + swsh[1] * b2[c] + swsh[2] * b3[c] + swsh[3] * b4[c]
                    + swsh[4] * (nf[b][4][c] + b5[c]);       // f5 value (constant map)
            float m = fusion_w[co * CMID + c] * fnsh[b][c];
            g_M[(b * COUT + co) * CMID + c] = m;
            bt += m * K;
        }
        g_beta[b * COUT + co] = bt;
    }

    // ---- phase 5: folded 25-tap stage-1 weights, scaled by softmax weights ----
    for (int idx = tid; idx < CIN * NTAPS * CMID; idx += 256) {
        int ci = idx / (NTAPS * CMID);
        int r = idx - ci * (NTAPS * CMID);
        int t = r >> 4;
        int c = r & 15;
        int dyo, dx;
        if (t < 9)       { int g = t / 3; dyo = g - 3; dx = (t - g * 3 - 1) * (3 - g); }
        else if (t < 16) { dyo = 0; dx = t - 12; }
        else             { int g = (t - 16) / 3; dyo = g + 1; dx = ((t - 16) - g * 3 - 1) * (g + 1); }
        float v = 0.f;
        if (dyo == 0 && dx == 0) v += swsh[0] * w1[c * CIN + ci];
        for (int d = 1; d <= 3; ++d) {
            const float* wd = (d == 1) ? w2 : (d == 2) ? w3 : w4;
            bool iny = (dyo == 0 || dyo == d || dyo == -d);
            bool inx = (dx  == 0 || dx  == d || dx  == -d);
            if (iny && inx) {
                int ky = dyo / d + 1, kx = dx / d + 1;
                v += swsh[d] * wd[(c * CIN + ci) * 9 + ky * 3 + kx];
            }
        }
        g_W25[idx] = v;
    }
}

// ============================================================
// Kernel C: fused 25-tap conv (32->16) + pointwise (16->32) per batch.
// Tile: 128x8 pixels, 256 threads, 4 px/thread, halo 3.
// Inner math uses packed fma.rn.f32x2 over adjacent mid-channel pairs.
// ============================================================
#define TX 128
#define TY 8
#define XS_STRIDE 136   // TX + 6 halo + 2 pad (keeps float4 reads in-bounds)
#define XS_ROWS   14    // TY + 6
#define SMEM_W25  (CIN * NTAPS * CMID)             // 12800
#define SMEM_M    (COUT * CMID)                    // 512
#define SMEM_FLOATS (SMEM_W25 + SMEM_M + COUT + XS_ROWS * XS_STRIDE)  // 15248

__global__ void __launch_bounds__(256, 2)
main_kernel(const float* __restrict__ x, float* __restrict__ y) {
    extern __shared__ float smem[];
    float* Wsh    = smem;                       // [ci][tap][c] 12800
    float* Msh    = smem + SMEM_W25;            // 512
    float* betash = Msh + SMEM_M;               // 32
    float* xs     = betash + COUT;              // 14 x 136

    const int b  = blockIdx.z;
    const int h0 = blockIdx.y * TY;
    const int w0 = blockIdx.x * TX;
    const int tid = threadIdx.x;
    const int ty  = tid >> 5;      // 0..7
    const int tx4 = tid & 31;      // 0..31; pixels w0 + tx4*4 + {0..3}

    for (int i = tid; i < SMEM_W25; i += 256) Wsh[i] = g_W25[i];
    for (int i = tid; i < SMEM_M;   i += 256) Msh[i] = g_M[b * SMEM_M + i];
    if (tid < COUT) betash[tid] = g_beta[b * COUT + tid];

    // acc pairs over adjacent mid-channels: accp[cp][p] holds (c=2cp, c=2cp+1) for pixel p
    ull accp[CMID / 2][4];
#pragma unroll
    for (int cp = 0; cp < CMID / 2; ++cp)
#pragma unroll
        for (int p = 0; p < 4; ++p) accp[cp][p] = 0ull;

#pragma unroll 1
    for (int ci = 0; ci < CIN; ++ci) {
        __syncthreads();
        // fill x tile (halo 3, zero pad outside image)
        const float* xp = x + (size_t)(b * CIN + ci) * PLANE;
        for (int i = tid; i < XS_ROWS * XS_STRIDE; i += 256) {
            int r  = i / XS_STRIDE;
            int cc = i - r * XS_STRIDE;
            int h = h0 - 3 + r;
            int w = w0 - 3 + cc;
            float v = 0.f;
            if ((unsigned)h < HH && (unsigned)w < WW) v = xp[h * WW + w];
            xs[i] = v;
        }
        __syncthreads();

        const float* wci = Wsh + ci * (NTAPS * CMID);
        const float* xbase = xs + ty * XS_STRIDE + tx4 * 4;

#pragma unroll
        for (int dyi = 0; dyi < 7; ++dyi) {
            const float4 a0 = *(const float4*)(xbase + dyi * XS_STRIDE);
            const float4 a1 = *(const float4*)(xbase + dyi * XS_STRIDE + 4);
            const float4 a2 = *(const float4*)(xbase + dyi * XS_STRIDE + 8);
            const float xr[10] = {a0.x, a0.y, a0.z, a0.w, a1.x, a1.y, a1.z, a1.w,
                                  a2.x, a2.y};
            ull xb[10];  // broadcast pairs {x,x}
#pragma unroll
            for (int k = 0; k < 10; ++k) PACKF2(xb[k], xr[k], xr[k]);

            const int aD = (dyi < 3) ? (3 - dyi) : (dyi - 3);
            const int nt = (dyi == 3) ? 7 : 3;
            const int tb = (dyi < 3) ? 3 * dyi : ((dyi == 3) ? 9 : 16 + 3 * (dyi - 4));
#pragma unroll
            for (int k = 0; k < nt; ++k) {
                const int dx = (dyi == 3) ? (k - 3) : ((k - 1) * aD);
                const ull* wt = (const ull*)(wci + (tb + k) * CMID);
#pragma unroll
                for (int cp = 0; cp < CMID / 2; ++cp) {
                    const ull w2v = wt[cp];   // LDS.64 of {w[2cp], w[2cp+1]} (warp broadcast)
                    FFMA2(accp[cp][0], w2v, xb[3 + dx]);
                    FFMA2(accp[cp][1], w2v, xb[4 + dx]);
                    FFMA2(accp[cp][2], w2v, xb[5 + dx]);
                    FFMA2(accp[cp][3], w2v, xb[6 + dx]);
                }
            }
        }
    }

    // ---- epilogue: y[co] = sum_c M[co][c]*acc[c] + beta[co], packed over c pairs ----
    const int h = h0 + ty;
    float* yp = y + ((size_t)(b * COUT) * HH + h) * WW + w0 + tx4 * 4;
#pragma unroll 1
    for (int co = 0; co < COUT; ++co) {
        const ull* m64 = (const ull*)(Msh + co * CMID);
        ull o[4] = {0ull, 0ull, 0ull, 0ull};
#pragma unroll
        for (int cp = 0; cp < CMID / 2; ++cp) {
            const ull mv = m64[cp];
            FFMA2(o[0], mv, accp[cp][0]);
            FFMA2(o[1], mv, accp[cp][1]);
            FFMA2(o[2], mv, accp[cp][2]);
            FFMA2(o[3], mv, accp[cp][3]);
        }
        const float bt = betash[co];
        float4 ov;
        {
            float lo, hi;
            UNPACKF2(lo, hi, o[0]); ov.x = lo + hi + bt;
            UNPACKF2(lo, hi, o[1]); ov.y = lo + hi + bt;
            UNPACKF2(lo, hi, o[2]); ov.z = lo + hi + bt;
            UNPACKF2(lo, hi, o[3]); ov.w = lo + hi + bt;
        }
        *(float4*)(yp + (size_t)co * PLANE) = ov;
    }
}

// ============================================================
extern "C" void kernel_launch(void* const* d_in, const int* in_sizes, int n_in,
                              void* d_out, int out_size) {
    const float* x        = (const float*)d_in[0];
    const float* w1       = (const float*)d_in[1];
    const float* b1       = (const float*)d_in[2];
    const float* w2       = (const float*)d_in[3];
    const float* b2       = (const float*)d_in[4];
    const float* w3       = (const float*)d_in[5];
    const float* b3       = (const float*)d_in[6];
    const float* w4       = (const float*)d_in[7];
    const float* b4       = (const float*)d_in[8];
    const float* w5       = (const float*)d_in[9];
    const float* b5       = (const float*)d_in[10];
    const float* gcn_w    = (const float*)d_in[11];
    const float* gcn_b    = (const float*)d_in[12];
    const float* attn     = (const float*)d_in[13];
    const float* fusion_w = (const float*)d_in[14];
    const float* fusion_b = (const float*)d_in[15];
    float* y = (float*)d_out;

    static_assert(SMEM_FLOATS * 4 < 228 * 1024, "smem");
    cudaFuncSetAttribute(main_kernel, cudaFuncAttributeMaxDynamicSharedMemorySize,
                         SMEM_FLOATS * 4);

    stats_kernel<<<NPLANES * NSLICE, 256>>>(x);
    prep_kernel<<<1, 256>>>(x, w1, b1, w2, b2, w3, b3, w4, b4, w5, b5,
                            gcn_w, gcn_b, attn, fusion_w, fusion_b);
    dim3 grid(WW / TX, HH / TY, BATCH);
    main_kernel<<<grid, 256, SMEM_FLOATS * 4>>>(x, y);
}

// round 8
// speedup vs baseline: 1.1688x; 1.1688x over previous
#include <cuda_runtime.h>
#include <cuda_bf16.h>
#include <math.h>

// Problem constants
#define BATCH 8
#define CIN   32
#define CMID  16
#define COUT  32
#define HH    384
#define WW    384
#define PLANE (HH*WW)            // 147456
#define NPLANES (BATCH*CIN)      // 256
#define NTAPS 25
#define NSLICE 8                 // row-slices per plane for stats
#define SLICE_ROWS 48
#define SLICE_F4 (SLICE_ROWS*WW/4)   // 4608 float4 per slice

typedef unsigned long long ull;

// packed f32x2 helpers
#define FFMA2(acc, a, b) asm("fma.rn.f32x2 %0, %1, %2, %0;" : "+l"(acc) : "l"(a), "l"(b))
#define PACKF2(out, lo, hi) asm("mov.b64 %0, {%1, %2};" : "=l"(out) : "f"(lo), "f"(hi))
#define UNPACKF2(lo, hi, in) asm("mov.b64 {%0, %1}, %2;" : "=f"(lo), "=f"(hi) : "l"(in))

// ---- scratch (device globals; no allocation allowed) ----
__device__ float g_part[NPLANES * NSLICE * 13];  // per (plane,slice) partial stats
__device__ float g_W25[CIN * NTAPS * CMID];      // folded stage-1 conv weights [ci][tap][c]
__device__ float g_M[BATCH * COUT * CMID];       // per-batch pointwise weights
__device__ float g_beta[BATCH * COUT];           // per-batch bias

// folded stage-1 weights in constant memory as 64-bit pairs -> LDCU/uniform path.
// cW25u[(ci*25 + tap)*8 + cp] = {W25[ci][tap][2cp], W25[ci][tap][2cp+1]}
__constant__ ull cW25u[CIN * NTAPS * CMID / 2];  // 6400 * 8B = 51200B

// ============================================================
// Kernel A: per-slice stats. grid = 2048 blocks (plane*8+slice), 256 threads.
// st layout: [0]=T, [1..3]=rowsum 0..2, [4..6]=rowsum 381..383,
//            [7..9]=colsum 0..2, [10..12]=colsum 381..383
// ============================================================
__device__ __forceinline__ float warp_red(float v) {
#pragma unroll
    for (int o = 16; o > 0; o >>= 1) v += __shfl_xor_sync(0xffffffffu, v, o);
    return v;
}

__global__ void stats_kernel(const float* __restrict__ x) {
    int blk = blockIdx.x;
    int plane = blk >> 3, slice = blk & 7;
    const float4* xp = (const float4*)(x + (size_t)plane * PLANE + (size_t)slice * SLICE_ROWS * WW);
    int tid = threadIdx.x;
    const bool bnd = (slice == 0 || slice == 7);

    float T = 0.f, c0 = 0.f, c1 = 0.f, c2 = 0.f, c3 = 0.f, c4 = 0.f, c5 = 0.f;
    float r0 = 0.f, r1 = 0.f, r2 = 0.f;

#pragma unroll
    for (int it = 0; it < SLICE_F4 / 256; ++it) {
        int i = tid + it * 256;
        float4 v = xp[i];
        float s4 = v.x + v.y + v.z + v.w;
        T += s4;
        int cq = i % 96;
        if (cq == 0)  { c0 += v.x; c1 += v.y; c2 += v.z; }
        if (cq == 95) { c3 += v.y; c4 += v.z; c5 += v.w; }
        if (bnd) {
            int lr = i / 96;                 // local row 0..47
            int key = (slice == 0) ? lr : (47 - lr);   // 0,1,2 are boundary rows
            if (key == 0) r0 += s4;          // row 0 / row 383
            else if (key == 1) r1 += s4;     // row 1 / row 382
            else if (key == 2) r2 += s4;     // row 2 / row 381
        }
    }

    __shared__ float s13[13];
    if (tid < 13) s13[tid] = 0.f;
    __syncthreads();

    T = warp_red(T);
    c0 = warp_red(c0); c1 = warp_red(c1); c2 = warp_red(c2);
    c3 = warp_red(c3); c4 = warp_red(c4); c5 = warp_red(c5);
    if (bnd) { r0 = warp_red(r0); r1 = warp_red(r1); r2 = warp_red(r2); }

    if ((tid & 31) == 0) {
        atomicAdd(&s13[0], T);
        atomicAdd(&s13[7], c0);  atomicAdd(&s13[8], c1);  atomicAdd(&s13[9], c2);
        atomicAdd(&s13[10], c3); atomicAdd(&s13[11], c4); atomicAdd(&s13[12], c5);
        if (bnd) {
            if (slice == 0) {
                atomicAdd(&s13[1], r0); atomicAdd(&s13[2], r1); atomicAdd(&s13[3], r2);
            } else {
                atomicAdd(&s13[6], r0); atomicAdd(&s13[5], r1); atomicAdd(&s13[4], r2);
            }
        }
    }
    __syncthreads();
    if (tid < 13) g_part[blk * 13 + tid] = s13[tid];
}

// partial sum of x over the valid shifted region for offset (dy,dx), exact borders
__device__ __forceinline__ float ps_fun(const float* __restrict__ xp,
                                        const float* __restrict__ st,
                                        int dy, int dx) {
    float s = st[0];
    if (dy > 0)      { for (int r = 0; r <  dy; ++r) s -= st[1 + r]; }
    else if (dy < 0) { for (int r = 0; r < -dy; ++r) s -= st[6 - r]; }
    if (dx > 0)      { for (int c = 0; c <  dx; ++c) s -= st[7 + c]; }
    else if (dx < 0) { for (int c = 0; c < -dx; ++c) s -= st[12 - c]; }
    if (dy != 0 && dx != 0) {
        int r0 = (dy > 0) ? 0 : HH + dy;
        int r1 = (dy > 0) ? dy - 1 : HH - 1;
        int c0 = (dx > 0) ? 0 : WW + dx;
        int c1 = (dx > 0) ? dx - 1 : WW - 1;
        for (int r = r0; r <= r1; ++r)
            for (int c = c0; c <= c1; ++c)
                s += xp[r * WW + c];  // add back doubly-subtracted corner
    }
    return s;
}

// ============================================================
// Kernel B: fold everything into W25 / M / beta. 1 block, 256 threads.
// ============================================================
__global__ void prep_kernel(const float* __restrict__ x,
                            const float* __restrict__ w1, const float* __restrict__ b1,
                            const float* __restrict__ w2, const float* __restrict__ b2,
                            const float* __restrict__ w3, const float* __restrict__ b3,
                            const float* __restrict__ w4, const float* __restrict__ b4,
                            const float* __restrict__ w5, const float* __restrict__ b5,
                            const float* __restrict__ gcn_w, const float* __restrict__ gcn_b,
                            const float* __restrict__ attn,
                            const float* __restrict__ fusion_w, const float* __restrict__ fusion_b) {
    __shared__ float nf[BATCH][5][CMID];   // branch node-feats WITHOUT biases
    __shared__ float zsh[BATCH][CMID];
    __shared__ float fnsh[BATCH][CMID];
    __shared__ float swsh[5];
    int tid = threadIdx.x;

    for (int i = tid; i < BATCH * 5 * CMID; i += 256) ((float*)nf)[i] = 0.f;
    if (tid == 0) {
        float m = attn[0];
        for (int i = 1; i < 5; ++i) m = fmaxf(m, attn[i]);
        float e[5], s = 0.f;
        for (int i = 0; i < 5; ++i) { e[i] = expf(attn[i] - m); s += e[i]; }
        for (int i = 0; i < 5; ++i) swsh[i] = e[i] / s;
    }
    __syncthreads();

    // ---- phase 1: exact per-branch node features (means with zero-padding) ----
    {
        int b = tid >> 5, ci = tid & 31;
        int plane = b * CIN + ci;
        const float* xp = x + (size_t)plane * PLANE;
        float st[13];
        for (int i = 0; i < 13; ++i) {
            float s = 0.f;
            for (int sl = 0; sl < NSLICE; ++sl) s += g_part[(plane * NSLICE + sl) * 13 + i];
            st[i] = s;
        }
        const float invHW = 1.0f / (float)PLANE;
        float xm = st[0] * invHW;
        for (int c = 0; c < CMID; ++c) {
            atomicAdd(&nf[b][0][c], w1[c * CIN + ci] * xm);   // f1: 1x1
            atomicAdd(&nf[b][4][c], w5[c * CIN + ci] * xm);   // f5: 1x1 on GAP
        }
        for (int d = 1; d <= 3; ++d) {
            float ps[9];
            for (int ky = 0; ky < 3; ++ky)
                for (int kx = 0; kx < 3; ++kx)
                    ps[ky * 3 + kx] = ps_fun(xp, st, d * (ky - 1), d * (kx - 1)) * invHW;
            const float* wd = (d == 1) ? w2 : (d == 2) ? w3 : w4;
            for (int c = 0; c < CMID; ++c) {
                float p = 0.f;
                for (int j = 0; j < 9; ++j) p += wd[(c * CIN + ci) * 9 + j] * ps[j];
                atomicAdd(&nf[b][d][c], p);
            }
        }
    }
    __syncthreads();

    // ---- phase 2: z = mean over branches (A_hat uniform) incl. biases ----
    if (tid < BATCH * CMID) {
        int b = tid >> 4, c = tid & 15;
        float s = nf[b][0][c] + nf[b][1][c] + nf[b][2][c] + nf[b][3][c] + nf[b][4][c]
                + b1[c] + b2[c] + b3[c] + b4[c] + b5[c];
        zsh[b][c] = 0.2f * s;
    }
    __syncthreads();

    // ---- phase 3: fn = z @ gcn_w + gcn_b ----
    if (tid < BATCH * CMID) {
        int b = tid >> 4, c = tid & 15;
        float s = gcn_b[c];
        for (int k = 0; k < CMID; ++k) s += zsh[b][k] * gcn_w[k * CMID + c];
        fnsh[b][c] = s;
    }
    __syncthreads();

    // ---- phase 4: M, beta ----
    {
        int b = tid >> 5, co = tid & 31;
        float bt = fusion_b[co];
        for (int c = 0; c < CMID; ++c) {
            float K = swsh[0] * b1[c] + swsh[1] * b2[c] + swsh[2] * b3[c] + swsh[3] * b4[c]
                    + swsh[4] * (nf[b][4][c] + b5[c]);       // f5 value (constant map)
            float m = fusion_w[co * CMID + c] * fnsh[b][c];
            g_M[(b * COUT + co) * CMID + c] = m;
            bt += m * K;
        }
        g_beta[b * COUT + co] = bt;
    }

    // ---- phase 5: folded 25-tap stage-1 weights, scaled by softmax weights ----
    for (int idx = tid; idx < CIN * NTAPS * CMID; idx += 256) {
        int ci = idx / (NTAPS * CMID);
        int r = idx - ci * (NTAPS * CMID);
        int t = r >> 4;
        int c = r & 15;
        int dyo, dx;
        if (t < 9)       { int g = t / 3; dyo = g - 3; dx = (t - g * 3 - 1) * (3 - g); }
        else if (t < 16) { dyo = 0; dx = t - 12; }
        else             { int g = (t - 16) / 3; dyo = g + 1; dx = ((t - 16) - g * 3 - 1) * (g + 1); }
        float v = 0.f;
        if (dyo == 0 && dx == 0) v += swsh[0] * w1[c * CIN + ci];
        for (int d = 1; d <= 3; ++d) {
            const float* wd = (d == 1) ? w2 : (d == 2) ? w3 : w4;
            bool iny = (dyo == 0 || dyo == d || dyo == -d);
            bool inx = (dx  == 0 || dx  == d || dx  == -d);
            if (iny && inx) {
                int ky = dyo / d + 1, kx = dx / d + 1;
                v += swsh[d] * wd[(c * CIN + ci) * 9 + ky * 3 + kx];
            }
        }
        g_W25[idx] = v;
    }
}

// ============================================================
// Kernel C: fused 25-tap conv (32->16) + pointwise (16->32) per batch.
// Tile: 128x8 pixels, 256 threads, 4 px/thread, halo 3.
// Weights come from __constant__ (LDCU/uniform path); x tile is
// register-prefetch double-buffered so LDG latency overlaps compute.
// ============================================================
#define TX 128
#define TY 8
#define XS_STRIDE 136   // TX + 6 halo + 2 pad (keeps float4 reads in-bounds)
#define XS_ROWS   14    // TY + 6
#define NXS (XS_ROWS * XS_STRIDE)                  // 1904
#define SMEM_M    (COUT * CMID)                    // 512
#define SMEM_FLOATS (SMEM_M + COUT + NXS)          // 2448

__global__ void __launch_bounds__(256, 2)
main_kernel(const float* __restrict__ x, float* __restrict__ y) {
    extern __shared__ float smem[];
    float* Msh    = smem;                       // 512
    float* betash = Msh + SMEM_M;               // 32
    float* xs     = betash + COUT;              // 14 x 136

    const int b  = blockIdx.z;
    const int h0 = blockIdx.y * TY;
    const int w0 = blockIdx.x * TX;
    const int tid = threadIdx.x;
    const int ty  = tid >> 5;      // 0..7
    const int tx4 = tid & 31;      // 0..31; pixels w0 + tx4*4 + {0..3}

    for (int i = tid; i < SMEM_M; i += 256) Msh[i] = g_M[b * SMEM_M + i];
    if (tid < COUT) betash[tid] = g_beta[b * COUT + tid];

    // acc pairs over adjacent mid-channels: accp[cp][p] holds (c=2cp, c=2cp+1) for pixel p
    ull accp[CMID / 2][4];
#pragma unroll
    for (int cp = 0; cp < CMID / 2; ++cp)
#pragma unroll
        for (int p = 0; p < 4; ++p) accp[cp][p] = 0ull;

    // ---- initial fill of x tile for ci = 0 ----
    {
        const float* xp = x + (size_t)(b * CIN) * PLANE;
#pragma unroll
        for (int it = 0; it < 8; ++it) {
            int i = tid + it * 256;
            if (i < NXS) {
                int r  = i / XS_STRIDE;
                int cc = i - r * XS_STRIDE;
                int h = h0 - 3 + r;
                int w = w0 - 3 + cc;
                float v = 0.f;
                if ((unsigned)h < HH && (unsigned)w < WW) v = xp[h * WW + w];
                xs[i] = v;
            }
        }
    }

#pragma unroll 1
    for (int ci = 0; ci < CIN; ++ci) {
        __syncthreads();   // xs (stores from prev iter / initial fill) visible

        // prefetch next ci's tile into registers; LDGs overlap the compute below
        float pf[8];
        if (ci + 1 < CIN) {
            const float* xq = x + (size_t)(b * CIN + ci + 1) * PLANE;
#pragma unroll
            for (int it = 0; it < 8; ++it) {
                int i = tid + it * 256;
                float v = 0.f;
                if (i < NXS) {
                    int r  = i / XS_STRIDE;
                    int cc = i - r * XS_STRIDE;
                    int h = h0 - 3 + r;
                    int w = w0 - 3 + cc;
                    if ((unsigned)h < HH && (unsigned)w < WW) v = xq[h * WW + w];
                }
                pf[it] = v;
            }
        }

        const ull* wci = cW25u + ci * (NTAPS * CMID / 2);
        const float* xbase = xs + ty * XS_STRIDE + tx4 * 4;

#pragma unroll
        for (int dyi = 0; dyi < 7; ++dyi) {
            const float4 a0 = *(const float4*)(xbase + dyi * XS_STRIDE);
            const float4 a1 = *(const float4*)(xbase + dyi * XS_STRIDE + 4);
            const float4 a2 = *(const float4*)(xbase + dyi * XS_STRIDE + 8);
            const float xr[10] = {a0.x, a0.y, a0.z, a0.w, a1.x, a1.y, a1.z, a1.w,
                                  a2.x, a2.y};
            ull xb[10];  // broadcast pairs {x,x}
#pragma unroll
            for (int k = 0; k < 10; ++k) PACKF2(xb[k], xr[k], xr[k]);

            const int aD = (dyi < 3) ? (3 - dyi) : (dyi - 3);
            const int nt = (dyi == 3) ? 7 : 3;
            const int tb = (dyi < 3) ? 3 * dyi : ((dyi == 3) ? 9 : 16 + 3 * (dyi - 4));
#pragma unroll
            for (int k = 0; k < nt; ++k) {
                const int dx = (dyi == 3) ? (k - 3) : ((k - 1) * aD);
                const ull* wt = wci + (tb + k) * (CMID / 2);
#pragma unroll
                for (int cp = 0; cp < CMID / 2; ++cp) {
                    const ull w2v = wt[cp];   // ld.const.u64, warp-uniform -> LDCU/UR
                    FFMA2(accp[cp][0], w2v, xb[3 + dx]);
                    FFMA2(accp[cp][1], w2v, xb[4 + dx]);
                    FFMA2(accp[cp][2], w2v, xb[5 + dx]);
                    FFMA2(accp[cp][3], w2v, xb[6 + dx]);
                }
            }
        }

        __syncthreads();   // everyone done reading xs
        if (ci + 1 < CIN) {
#pragma unroll
            for (int it = 0; it < 8; ++it) {
                int i = tid + it * 256;
                if (i < NXS) xs[i] = pf[it];
            }
        }
    }

    // ---- epilogue: y[co] = sum_c M[co][c]*acc[c] + beta[co], packed over c pairs ----
    const int h = h0 + ty;
    float* yp = y + ((size_t)(b * COUT) * HH + h) * WW + w0 + tx4 * 4;
#pragma unroll 1
    for (int co = 0; co < COUT; ++co) {
        const ull* m64 = (const ull*)(Msh + co * CMID);
        ull o[4] = {0ull, 0ull, 0ull, 0ull};
#pragma unroll
        for (int cp = 0; cp < CMID / 2; ++cp) {
            const ull mv = m64[cp];
            FFMA2(o[0], mv, accp[cp][0]);
            FFMA2(o[1], mv, accp[cp][1]);
            FFMA2(o[2], mv, accp[cp][2]);
            FFMA2(o[3], mv, accp[cp][3]);
        }
        const float bt = betash[co];
        float4 ov;
        {
            float lo, hi;
            UNPACKF2(lo, hi, o[0]); ov.x = lo + hi + bt;
            UNPACKF2(lo, hi, o[1]); ov.y = lo + hi + bt;
            UNPACKF2(lo, hi, o[2]); ov.z = lo + hi + bt;
            UNPACKF2(lo, hi, o[3]); ov.w = lo + hi + bt;
        }
        *(float4*)(yp + (size_t)co * PLANE) = ov;
    }
}

// ============================================================
extern "C" void kernel_launch(void* const* d_in, const int* in_sizes, int n_in,
                              void* d_out, int out_size) {
    const float* x        = (const float*)d_in[0];
    const float* w1       = (const float*)d_in[1];
    const float* b1       = (const float*)d_in[2];
    const float* w2       = (const float*)d_in[3];
    const float* b2       = (const float*)d_in[4];
    const float* w3       = (const float*)d_in[5];
    const float* b3       = (const float*)d_in[6];
    const float* w4       = (const float*)d_in[7];
    const float* b4       = (const float*)d_in[8];
    const float* w5       = (const float*)d_in[9];
    const float* b5       = (const float*)d_in[10];
    const float* gcn_w    = (const float*)d_in[11];
    const float* gcn_b    = (const float*)d_in[12];
    const float* attn     = (const float*)d_in[13];
    const float* fusion_w = (const float*)d_in[14];
    const float* fusion_b = (const float*)d_in[15];
    float* y = (float*)d_out;

    cudaFuncSetAttribute(main_kernel, cudaFuncAttributeMaxDynamicSharedMemorySize,
                         SMEM_FLOATS * 4);

    stats_kernel<<<NPLANES * NSLICE, 256>>>(x);
    prep_kernel<<<1, 256>>>(x, w1, b1, w2, b2, w3, b3, w4, b4, w5, b5,
                            gcn_w, gcn_b, attn, fusion_w, fusion_b);

    // bridge folded weights into constant memory (graph-capturable D2D copy)
    void* w25_dev = nullptr;
    cudaGetSymbolAddress(&w25_dev, g_W25);
    cudaMemcpyToSymbolAsync(cW25u, w25_dev, CIN * NTAPS * CMID * sizeof(float), 0,
                            cudaMemcpyDeviceToDevice, 0);

    dim3 grid(WW / TX, HH / TY, BATCH);
    main_kernel<<<grid, 256, SMEM_FLOATS * 4>>>(x, y);
}

// round 9
// speedup vs baseline: 1.1709x; 1.0018x over previous
#include <cuda_runtime.h>
#include <cuda_bf16.h>
#include <math.h>

// Problem constants
#define BATCH 8
#define CIN   32
#define CMID  16
#define COUT  32
#define HH    384
#define WW    384
#define PLANE (HH*WW)            // 147456
#define NPLANES (BATCH*CIN)      // 256
#define NTAPS 25
#define NSLICE 8                 // row-slices per plane for stats
#define SLICE_ROWS 48
#define SLICE_F4 (SLICE_ROWS*WW/4)   // 4608 float4 per slice

typedef unsigned long long ull;

// packed f32x2 helpers
#define FFMA2(acc, a, b) asm("fma.rn.f32x2 %0, %1, %2, %0;" : "+l"(acc) : "l"(a), "l"(b))
#define PACKF2(out, lo, hi) asm("mov.b64 %0, {%1, %2};" : "=l"(out) : "f"(lo), "f"(hi))
#define UNPACKF2(lo, hi, in) asm("mov.b64 {%0, %1}, %2;" : "=f"(lo), "=f"(hi) : "l"(in))

// ---- scratch (device globals; no allocation allowed) ----
__device__ float g_part[NPLANES * NSLICE * 13];  // per (plane,slice) partial stats
__device__ float g_W25[CIN * NTAPS * CMID];      // folded stage-1 conv weights [ci][tap][c]
__device__ float g_M[BATCH * COUT * CMID];       // per-batch pointwise weights
__device__ float g_beta[BATCH * COUT];           // per-batch bias

// folded stage-1 weights in constant memory as 64-bit pairs -> LDCU/uniform path.
// cW25u[(ci*25 + tap)*8 + cp] = {W25[ci][tap][2cp], W25[ci][tap][2cp+1]}
__constant__ ull cW25u[CIN * NTAPS * CMID / 2];  // 6400 * 8B = 51200B

// ============================================================
// Kernel A: per-slice stats. grid = 2048 blocks (plane*8+slice), 256 threads.
// st layout: [0]=T, [1..3]=rowsum 0..2, [4..6]=rowsum 381..383,
//            [7..9]=colsum 0..2, [10..12]=colsum 381..383
// ============================================================
__device__ __forceinline__ float warp_red(float v) {
#pragma unroll
    for (int o = 16; o > 0; o >>= 1) v += __shfl_xor_sync(0xffffffffu, v, o);
    return v;
}

__global__ void stats_kernel(const float* __restrict__ x) {
    int blk = blockIdx.x;
    int plane = blk >> 3, slice = blk & 7;
    const float4* xp = (const float4*)(x + (size_t)plane * PLANE + (size_t)slice * SLICE_ROWS * WW);
    int tid = threadIdx.x;
    const bool bnd = (slice == 0 || slice == 7);

    float T = 0.f, c0 = 0.f, c1 = 0.f, c2 = 0.f, c3 = 0.f, c4 = 0.f, c5 = 0.f;
    float r0 = 0.f, r1 = 0.f, r2 = 0.f;

#pragma unroll
    for (int it = 0; it < SLICE_F4 / 256; ++it) {
        int i = tid + it * 256;
        float4 v = xp[i];
        float s4 = v.x + v.y + v.z + v.w;
        T += s4;
        int cq = i % 96;
        if (cq == 0)  { c0 += v.x; c1 += v.y; c2 += v.z; }
        if (cq == 95) { c3 += v.y; c4 += v.z; c5 += v.w; }
        if (bnd) {
            int lr = i / 96;                 // local row 0..47
            int key = (slice == 0) ? lr : (47 - lr);   // 0,1,2 are boundary rows
            if (key == 0) r0 += s4;          // row 0 / row 383
            else if (key == 1) r1 += s4;     // row 1 / row 382
            else if (key == 2) r2 += s4;     // row 2 / row 381
        }
    }

    __shared__ float s13[13];
    if (tid < 13) s13[tid] = 0.f;
    __syncthreads();

    T = warp_red(T);
    c0 = warp_red(c0); c1 = warp_red(c1); c2 = warp_red(c2);
    c3 = warp_red(c3); c4 = warp_red(c4); c5 = warp_red(c5);
    if (bnd) { r0 = warp_red(r0); r1 = warp_red(r1); r2 = warp_red(r2); }

    if ((tid & 31) == 0) {
        atomicAdd(&s13[0], T);
        atomicAdd(&s13[7], c0);  atomicAdd(&s13[8], c1);  atomicAdd(&s13[9], c2);
        atomicAdd(&s13[10], c3); atomicAdd(&s13[11], c4); atomicAdd(&s13[12], c5);
        if (bnd) {
            if (slice == 0) {
                atomicAdd(&s13[1], r0); atomicAdd(&s13[2], r1); atomicAdd(&s13[3], r2);
            } else {
                atomicAdd(&s13[6], r0); atomicAdd(&s13[5], r1); atomicAdd(&s13[4], r2);
            }
        }
    }
    __syncthreads();
    if (tid < 13) g_part[blk * 13 + tid] = s13[tid];
}

// partial sum of x over the valid shifted region for offset (dy,dx), exact borders
__device__ __forceinline__ float ps_fun(const float* __restrict__ xp,
                                        const float* __restrict__ st,
                                        int dy, int dx) {
    float s = st[0];
    if (dy > 0)      { for (int r = 0; r <  dy; ++r) s -= st[1 + r]; }
    else if (dy < 0) { for (int r = 0; r < -dy; ++r) s -= st[6 - r]; }
    if (dx > 0)      { for (int c = 0; c <  dx; ++c) s -= st[7 + c]; }
    else if (dx < 0) { for (int c = 0; c < -dx; ++c) s -= st[12 - c]; }
    if (dy != 0 && dx != 0) {
        int r0 = (dy > 0) ? 0 : HH + dy;
        int r1 = (dy > 0) ? dy - 1 : HH - 1;
        int c0 = (dx > 0) ? 0 : WW + dx;
        int c1 = (dx > 0) ? dx - 1 : WW - 1;
        for (int r = r0; r <= r1; ++r)
            for (int c = c0; c <= c1; ++c)
                s += xp[r * WW + c];  // add back doubly-subtracted corner
    }
    return s;
}

// ============================================================
// Kernel B: fold everything into W25 / M / beta. 1 block, 256 threads.
// ============================================================
__global__ void prep_kernel(const float* __restrict__ x,
                            const float* __restrict__ w1, const float* __restrict__ b1,
                            const float* __restrict__ w2, const float* __restrict__ b2,
                            const float* __restrict__ w3, const float* __restrict__ b3,
                            const float* __restrict__ w4, const float* __restrict__ b4,
                            const float* __restrict__ w5, const float* __restrict__ b5,
                            const float* __restrict__ gcn_w, const float* __restrict__ gcn_b,
                            const float* __restrict__ attn,
                            const float* __restrict__ fusion_w, const float* __restrict__ fusion_b) {
    __shared__ float nf[BATCH][5][CMID];   // branch node-feats WITHOUT biases
    __shared__ float zsh[BATCH][CMID];
    __shared__ float fnsh[BATCH][CMID];
    __shared__ float swsh[5];
    int tid = threadIdx.x;

    for (int i = tid; i < BATCH * 5 * CMID; i += 256) ((float*)nf)[i] = 0.f;
    if (tid == 0) {
        float m = attn[0];
        for (int i = 1; i < 5; ++i) m = fmaxf(m, attn[i]);
        float e[5], s = 0.f;
        for (int i = 0; i < 5; ++i) { e[i] = expf(attn[i] - m); s += e[i]; }
        for (int i = 0; i < 5; ++i) swsh[i] = e[i] / s;
    }
    __syncthreads();

    // ---- phase 1: exact per-branch node features (means with zero-padding) ----
    {
        int b = tid >> 5, ci = tid & 31;
        int plane = b * CIN + ci;
        const float* xp = x + (size_t)plane * PLANE;
        float st[13];
        for (int i = 0; i < 13; ++i) {
            float s = 0.f;
            for (int sl = 0; sl < NSLICE; ++sl) s += g_part[(plane * NSLICE + sl) * 13 + i];
            st[i] = s;
        }
        const float invHW = 1.0f / (float)PLANE;
        float xm = st[0] * invHW;
        for (int c = 0; c < CMID; ++c) {
            atomicAdd(&nf[b][0][c], w1[c * CIN + ci] * xm);   // f1: 1x1
            atomicAdd(&nf[b][4][c], w5[c * CIN + ci] * xm);   // f5: 1x1 on GAP
        }
        for (int d = 1; d <= 3; ++d) {
            float ps[9];
            for (int ky = 0; ky < 3; ++ky)
                for (int kx = 0; kx < 3; ++kx)
                    ps[ky * 3 + kx] = ps_fun(xp, st, d * (ky - 1), d * (kx - 1)) * invHW;
            const float* wd = (d == 1) ? w2 : (d == 2) ? w3 : w4;
            for (int c = 0; c < CMID; ++c) {
                float p = 0.f;
                for (int j = 0; j < 9; ++j) p += wd[(c * CIN + ci) * 9 + j] * ps[j];
                atomicAdd(&nf[b][d][c], p);
            }
        }
    }
    __syncthreads();

    // ---- phase 2: z = mean over branches (A_hat uniform) incl. biases ----
    if (tid < BATCH * CMID) {
        int b = tid >> 4, c = tid & 15;
        float s = nf[b][0][c] + nf[b][1][c] + nf[b][2][c] + nf[b][3][c] + nf[b][4][c]
                + b1[c] + b2[c] + b3[c] + b4[c] + b5[c];
        zsh[b][c] = 0.2f * s;
    }
    __syncthreads();

    // ---- phase 3: fn = z @ gcn_w + gcn_b ----
    if (tid < BATCH * CMID) {
        int b = tid >> 4, c = tid & 15;
        float s = gcn_b[c];
        for (int k = 0; k < CMID; ++k) s += zsh[b][k] * gcn_w[k * CMID + c];
        fnsh[b][c] = s;
    }
    __syncthreads();

    // ---- phase 4: M, beta ----
    {
        int b = tid >> 5, co = tid & 31;
        float bt = fusion_b[co];
        for (int c = 0; c < CMID; ++c) {
            float K = swsh[0] * b1[c] + swsh[1] * b2[c] + swsh[2] * b3[c] + swsh[3] * b4[c]
                    + swsh[4] * (nf[b][4][c] + b5[c]);       // f5 value (constant map)
            float m = fusion_w[co * CMID + c] * fnsh[b][c];
            g_M[(b * COUT + co) * CMID + c] = m;
            bt += m * K;
        }
        g_beta[b * COUT + co] = bt;
    }

    // ---- phase 5: folded 25-tap stage-1 weights, scaled by softmax weights ----
    for (int idx = tid; idx < CIN * NTAPS * CMID; idx += 256) {
        int ci = idx / (NTAPS * CMID);
        int r = idx - ci * (NTAPS * CMID);
        int t = r >> 4;
        int c = r & 15;
        int dyo, dx;
        if (t < 9)       { int g = t / 3; dyo = g - 3; dx = (t - g * 3 - 1) * (3 - g); }
        else if (t < 16) { dyo = 0; dx = t - 12; }
        else             { int g = (t - 16) / 3; dyo = g + 1; dx = ((t - 16) - g * 3 - 1) * (g + 1); }
        float v = 0.f;
        if (dyo == 0 && dx == 0) v += swsh[0] * w1[c * CIN + ci];
        for (int d = 1; d <= 3; ++d) {
            const float* wd = (d == 1) ? w2 : (d == 2) ? w3 : w4;
            bool iny = (dyo == 0 || dyo == d || dyo == -d);
            bool inx = (dx  == 0 || dx  == d || dx  == -d);
            if (iny && inx) {
                int ky = dyo / d + 1, kx = dx / d + 1;
                v += swsh[d] * wd[(c * CIN + ci) * 9 + ky * 3 + kx];
            }
        }
        g_W25[idx] = v;
    }
}

// ============================================================
// Kernel C: fused 25-tap conv (32->16) + pointwise (16->32) per batch.
// Tile: 128x8 pixels, 256 threads, 4 px/thread, halo 3.
// Weights come from __constant__ (LDCU/uniform path); x tile is
// register-prefetch double-buffered so LDG latency overlaps compute.
// ============================================================
#define TX 128
#define TY 8
#define XS_STRIDE 136   // TX + 6 halo + 2 pad (keeps float4 reads in-bounds)
#define XS_ROWS   14    // TY + 6
#define NXS (XS_ROWS * XS_STRIDE)                  // 1904
#define SMEM_M    (COUT * CMID)                    // 512
#define SMEM_FLOATS (SMEM_M + COUT + NXS)          // 2448

__global__ void __launch_bounds__(256, 2)
main_kernel(const float* __restrict__ x, float* __restrict__ y) {
    extern __shared__ float smem[];
    float* Msh    = smem;                       // 512
    float* betash = Msh + SMEM_M;               // 32
    float* xs     = betash + COUT;              // 14 x 136

    const int b  = blockIdx.z;
    const int h0 = blockIdx.y * TY;
    const int w0 = blockIdx.x * TX;
    const int tid = threadIdx.x;
    const int ty  = tid >> 5;      // 0..7
    const int tx4 = tid & 31;      // 0..31; pixels w0 + tx4*4 + {0..3}

    for (int i = tid; i < SMEM_M; i += 256) Msh[i] = g_M[b * SMEM_M + i];
    if (tid < COUT) betash[tid] = g_beta[b * COUT + tid];

    // acc pairs over adjacent mid-channels: accp[cp][p] holds (c=2cp, c=2cp+1) for pixel p
    ull accp[CMID / 2][4];
#pragma unroll
    for (int cp = 0; cp < CMID / 2; ++cp)
#pragma unroll
        for (int p = 0; p < 4; ++p) accp[cp][p] = 0ull;

    // ---- initial fill of x tile for ci = 0 ----
    {
        const float* xp = x + (size_t)(b * CIN) * PLANE;
#pragma unroll
        for (int it = 0; it < 8; ++it) {
            int i = tid + it * 256;
            if (i < NXS) {
                int r  = i / XS_STRIDE;
                int cc = i - r * XS_STRIDE;
                int h = h0 - 3 + r;
                int w = w0 - 3 + cc;
                float v = 0.f;
                if ((unsigned)h < HH && (unsigned)w < WW) v = xp[h * WW + w];
                xs[i] = v;
            }
        }
    }

#pragma unroll 1
    for (int ci = 0; ci < CIN; ++ci) {
        __syncthreads();   // xs (stores from prev iter / initial fill) visible

        // prefetch next ci's tile into registers; LDGs overlap the compute below
        float pf[8];
        if (ci + 1 < CIN) {
            const float* xq = x + (size_t)(b * CIN + ci + 1) * PLANE;
#pragma unroll
            for (int it = 0; it < 8; ++it) {
                int i = tid + it * 256;
                float v = 0.f;
                if (i < NXS) {
                    int r  = i / XS_STRIDE;
                    int cc = i - r * XS_STRIDE;
                    int h = h0 - 3 + r;
                    int w = w0 - 3 + cc;
                    if ((unsigned)h < HH && (unsigned)w < WW) v = xq[h * WW + w];
                }
                pf[it] = v;
            }
        }

        const ull* wci = cW25u + ci * (NTAPS * CMID / 2);
        const float* xbase = xs + ty * XS_STRIDE + tx4 * 4;

#pragma unroll
        for (int dyi = 0; dyi < 7; ++dyi) {
            const float4 a0 = *(const float4*)(xbase + dyi * XS_STRIDE);
            const float4 a1 = *(const float4*)(xbase + dyi * XS_STRIDE + 4);
            const float4 a2 = *(const float4*)(xbase + dyi * XS_STRIDE + 8);
            const float xr[10] = {a0.x, a0.y, a0.z, a0.w, a1.x, a1.y, a1.z, a1.w,
                                  a2.x, a2.y};
            ull xb[10];  // broadcast pairs {x,x}
#pragma unroll
            for (int k = 0; k < 10; ++k) PACKF2(xb[k], xr[k], xr[k]);

            const int aD = (dyi < 3) ? (3 - dyi) : (dyi - 3);
            const int nt = (dyi == 3) ? 7 : 3;
            const int tb = (dyi < 3) ? 3 * dyi : ((dyi == 3) ? 9 : 16 + 3 * (dyi - 4));
#pragma unroll
            for (int k = 0; k < nt; ++k) {
                const int dx = (dyi == 3) ? (k - 3) : ((k - 1) * aD);
                const ull* wt = wci + (tb + k) * (CMID / 2);
#pragma unroll
                for (int cp = 0; cp < CMID / 2; ++cp) {
                    const ull w2v = wt[cp];   // ld.const.u64, warp-uniform -> LDCU/UR
                    FFMA2(accp[cp][0], w2v, xb[3 + dx]);
                    FFMA2(accp[cp][1], w2v, xb[4 + dx]);
                    FFMA2(accp[cp][2], w2v, xb[5 + dx]);
                    FFMA2(accp[cp][3], w2v, xb[6 + dx]);
                }
            }
        }

        __syncthreads();   // everyone done reading xs
        if (ci + 1 < CIN) {
#pragma unroll
            for (int it = 0; it < 8; ++it) {
                int i = tid + it * 256;
                if (i < NXS) xs[i] = pf[it];
            }
        }
    }

    // ---- epilogue: y[co] = sum_c M[co][c]*acc[c] + beta[co], packed over c pairs ----
    const int h = h0 + ty;
    float* yp = y + ((size_t)(b * COUT) * HH + h) * WW + w0 + tx4 * 4;
#pragma unroll 1
    for (int co = 0; co < COUT; ++co) {
        const ull* m64 = (const ull*)(Msh + co * CMID);
        ull o[4] = {0ull, 0ull, 0ull, 0ull};
#pragma unroll
        for (int cp = 0; cp < CMID / 2; ++cp) {
            const ull mv = m64[cp];
            FFMA2(o[0], mv, accp[cp][0]);
            FFMA2(o[1], mv, accp[cp][1]);
            FFMA2(o[2], mv, accp[cp][2]);
            FFMA2(o[3], mv, accp[cp][3]);
        }
        const float bt = betash[co];
        float4 ov;
        {
            float lo, hi;
            UNPACKF2(lo, hi, o[0]); ov.x = lo + hi + bt;
            UNPACKF2(lo, hi, o[1]); ov.y = lo + hi + bt;
            UNPACKF2(lo, hi, o[2]); ov.z = lo + hi + bt;
            UNPACKF2(lo, hi, o[3]); ov.w = lo + hi + bt;
        }
        *(float4*)(yp + (size_t)co * PLANE) = ov;
    }
}

// ============================================================
extern "C" void kernel_launch(void* const* d_in, const int* in_sizes, int n_in,
                              void* d_out, int out_size) {
    const float* x        = (const float*)d_in[0];
    const float* w1       = (const float*)d_in[1];
    const float* b1       = (const float*)d_in[2];
    const float* w2       = (const float*)d_in[3];
    const float* b2       = (const float*)d_in[4];
    const float* w3       = (const float*)d_in[5];
    const float* b3       = (const float*)d_in[6];
    const float* w4       = (const float*)d_in[7];
    const float* b4       = (const float*)d_in[8];
    const float* w5       = (const float*)d_in[9];
    const float* b5       = (const float*)d_in[10];
    const float* gcn_w    = (const float*)d_in[11];
    const float* gcn_b    = (const float*)d_in[12];
    const float* attn     = (const float*)d_in[13];
    const float* fusion_w = (const float*)d_in[14];
    const float* fusion_b = (const float*)d_in[15];
    float* y = (float*)d_out;

    cudaFuncSetAttribute(main_kernel, cudaFuncAttributeMaxDynamicSharedMemorySize,
                         SMEM_FLOATS * 4);

    stats_kernel<<<NPLANES * NSLICE, 256>>>(x);
    prep_kernel<<<1, 256>>>(x, w1, b1, w2, b2, w3, b3, w4, b4, w5, b5,
                            gcn_w, gcn_b, attn, fusion_w, fusion_b);

    // bridge folded weights into constant memory (graph-capturable D2D copy)
    void* w25_dev = nullptr;
    cudaGetSymbolAddress(&w25_dev, g_W25);
    cudaMemcpyToSymbolAsync(cW25u, w25_dev, CIN * NTAPS * CMID * sizeof(float), 0,
                            cudaMemcpyDeviceToDevice, 0);

    dim3 grid(WW / TX, HH / TY, BATCH);
    main_kernel<<<grid, 256, SMEM_FLOATS * 4>>>(x, y);
}

// round 11
// speedup vs baseline: 1.1719x; 1.0009x over previous
#include <cuda_runtime.h>
#include <cuda_bf16.h>
#include <math.h>

// Problem constants
#define BATCH 8
#define CIN   32
#define CMID  16
#define COUT  32
#define HH    384
#define WW    384
#define PLANE (HH*WW)            // 147456
#define NPLANES (BATCH*CIN)      // 256
#define NTAPS 25
#define NSLICE 8                 // row-slices per plane for stats
#define SLICE_ROWS 48
#define SLICE_F4 (SLICE_ROWS*WW/4)   // 4608 float4 per slice

typedef unsigned long long ull;

// packed f32x2 helpers
#define FFMA2(acc, a, b) asm("fma.rn.f32x2 %0, %1, %2, %0;" : "+l"(acc) : "l"(a), "l"(b))
#define PACKF2(out, lo, hi) asm("mov.b64 %0, {%1, %2};" : "=l"(out) : "f"(lo), "f"(hi))
#define UNPACKF2(lo, hi, in) asm("mov.b64 {%0, %1}, %2;" : "=f"(lo), "=f"(hi) : "l"(in))

// ---- scratch (device globals; no allocation allowed) ----
__device__ float g_part[NPLANES * NSLICE * 13];  // per (plane,slice) partial stats
__device__ float g_W25[CIN * NTAPS * CMID];      // folded stage-1 conv weights [ci][tap][c]
__device__ float g_M[BATCH * COUT * CMID];       // per-batch pointwise weights
__device__ float g_beta[BATCH * COUT];           // per-batch bias

// folded stage-1 weights in constant memory as 64-bit pairs -> LDCU/uniform path.
// cW25u[(ci*25 + tap)*8 + cp] = {W25[ci][tap][2cp], W25[ci][tap][2cp+1]}
__constant__ ull cW25u[CIN * NTAPS * CMID / 2];  // 6400 * 8B = 51200B

// ============================================================
// Kernel A: per-slice stats. grid = 2048 blocks (plane*8+slice), 256 threads.
// st layout: [0]=T, [1..3]=rowsum 0..2, [4..6]=rowsum 381..383,
//            [7..9]=colsum 0..2, [10..12]=colsum 381..383
// ============================================================
__device__ __forceinline__ float warp_red(float v) {
#pragma unroll
    for (int o = 16; o > 0; o >>= 1) v += __shfl_xor_sync(0xffffffffu, v, o);
    return v;
}

__global__ void stats_kernel(const float* __restrict__ x) {
    int blk = blockIdx.x;
    int plane = blk >> 3, slice = blk & 7;
    const float4* xp = (const float4*)(x + (size_t)plane * PLANE + (size_t)slice * SLICE_ROWS * WW);
    int tid = threadIdx.x;
    const bool bnd = (slice == 0 || slice == 7);

    float T = 0.f, c0 = 0.f, c1 = 0.f, c2 = 0.f, c3 = 0.f, c4 = 0.f, c5 = 0.f;
    float r0 = 0.f, r1 = 0.f, r2 = 0.f;

#pragma unroll
    for (int it = 0; it < SLICE_F4 / 256; ++it) {
        int i = tid + it * 256;
        float4 v = xp[i];
        float s4 = v.x + v.y + v.z + v.w;
        T += s4;
        int cq = i % 96;
        if (cq == 0)  { c0 += v.x; c1 += v.y; c2 += v.z; }
        if (cq == 95) { c3 += v.y; c4 += v.z; c5 += v.w; }
        if (bnd) {
            int lr = i / 96;                 // local row 0..47
            int key = (slice == 0) ? lr : (47 - lr);   // 0,1,2 are boundary rows
            if (key == 0) r0 += s4;          // row 0 / row 383
            else if (key == 1) r1 += s4;     // row 1 / row 382
            else if (key == 2) r2 += s4;     // row 2 / row 381
        }
    }

    __shared__ float s13[13];
    if (tid < 13) s13[tid] = 0.f;
    __syncthreads();

    T = warp_red(T);
    c0 = warp_red(c0); c1 = warp_red(c1); c2 = warp_red(c2);
    c3 = warp_red(c3); c4 = warp_red(c4); c5 = warp_red(c5);
    if (bnd) { r0 = warp_red(r0); r1 = warp_red(r1); r2 = warp_red(r2); }

    if ((tid & 31) == 0) {
        atomicAdd(&s13[0], T);
        atomicAdd(&s13[7], c0);  atomicAdd(&s13[8], c1);  atomicAdd(&s13[9], c2);
        atomicAdd(&s13[10], c3); atomicAdd(&s13[11], c4); atomicAdd(&s13[12], c5);
        if (bnd) {
            if (slice == 0) {
                atomicAdd(&s13[1], r0); atomicAdd(&s13[2], r1); atomicAdd(&s13[3], r2);
            } else {
                atomicAdd(&s13[6], r0); atomicAdd(&s13[5], r1); atomicAdd(&s13[4], r2);
            }
        }
    }
    __syncthreads();
    if (tid < 13) g_part[blk * 13 + tid] = s13[tid];
}

// partial sum of x over the valid shifted region for offset (dy,dx), exact borders
__device__ __forceinline__ float ps_fun(const float* __restrict__ xp,
                                        const float* __restrict__ st,
                                        int dy, int dx) {
    float s = st[0];
    if (dy > 0)      { for (int r = 0; r <  dy; ++r) s -= st[1 + r]; }
    else if (dy < 0) { for (int r = 0; r < -dy; ++r) s -= st[6 - r]; }
    if (dx > 0)      { for (int c = 0; c <  dx; ++c) s -= st[7 + c]; }
    else if (dx < 0) { for (int c = 0; c < -dx; ++c) s -= st[12 - c]; }
    if (dy != 0 && dx != 0) {
        int r0 = (dy > 0) ? 0 : HH + dy;
        int r1 = (dy > 0) ? dy - 1 : HH - 1;
        int c0 = (dx > 0) ? 0 : WW + dx;
        int c1 = (dx > 0) ? dx - 1 : WW - 1;
        for (int r = r0; r <= r1; ++r)
            for (int c = c0; c <= c1; ++c)
                s += xp[r * WW + c];  // add back doubly-subtracted corner
    }
    return s;
}

// ============================================================
// Kernel B: fold everything into W25 / M / beta. 1 block, 256 threads.
// ============================================================
__global__ void prep_kernel(const float* __restrict__ x,
                            const float* __restrict__ w1, const float* __restrict__ b1,
                            const float* __restrict__ w2, const float* __restrict__ b2,
                            const float* __restrict__ w3, const float* __restrict__ b3,
                            const float* __restrict__ w4, const float* __restrict__ b4,
                            const float* __restrict__ w5, const float* __restrict__ b5,
                            const float* __restrict__ gcn_w, const float* __restrict__ gcn_b,
                            const float* __restrict__ attn,
                            const float* __restrict__ fusion_w, const float* __restrict__ fusion_b) {
    __shared__ float nf[BATCH][5][CMID];   // branch node-feats WITHOUT biases
    __shared__ float zsh[BATCH][CMID];
    __shared__ float fnsh[BATCH][CMID];
    __shared__ float swsh[5];
    int tid = threadIdx.x;

    for (int i = tid; i < BATCH * 5 * CMID; i += 256) ((float*)nf)[i] = 0.f;
    if (tid == 0) {
        float m = attn[0];
        for (int i = 1; i < 5; ++i) m = fmaxf(m, attn[i]);
        float e[5], s = 0.f;
        for (int i = 0; i < 5; ++i) { e[i] = expf(attn[i] - m); s += e[i]; }
        for (int i = 0; i < 5; ++i) swsh[i] = e[i] / s;
    }
    __syncthreads();

    // ---- phase 1: exact per-branch node features (means with zero-padding) ----
    {
        int b = tid >> 5, ci = tid & 31;
        int plane = b * CIN + ci;
        const float* xp = x + (size_t)plane * PLANE;
        float st[13];
        for (int i = 0; i < 13; ++i) {
            float s = 0.f;
            for (int sl = 0; sl < NSLICE; ++sl) s += g_part[(plane * NSLICE + sl) * 13 + i];
            st[i] = s;
        }
        const float invHW = 1.0f / (float)PLANE;
        float xm = st[0] * invHW;
        for (int c = 0; c < CMID; ++c) {
            atomicAdd(&nf[b][0][c], w1[c * CIN + ci] * xm);   // f1: 1x1
            atomicAdd(&nf[b][4][c], w5[c * CIN + ci] * xm);   // f5: 1x1 on GAP
        }
        for (int d = 1; d <= 3; ++d) {
            float ps[9];
            for (int ky = 0; ky < 3; ++ky)
                for (int kx = 0; kx < 3; ++kx)
                    ps[ky * 3 + kx] = ps_fun(xp, st, d * (ky - 1), d * (kx - 1)) * invHW;
            const float* wd = (d == 1) ? w2 : (d == 2) ? w3 : w4;
            for (int c = 0; c < CMID; ++c) {
                float p = 0.f;
                for (int j = 0; j < 9; ++j) p += wd[(c * CIN + ci) * 9 + j] * ps[j];
                atomicAdd(&nf[b][d][c], p);
            }
        }
    }
    __syncthreads();

    // ---- phase 2: z = mean over branches (A_hat uniform) incl. biases ----
    if (tid < BATCH * CMID) {
        int b = tid >> 4, c = tid & 15;
        float s = nf[b][0][c] + nf[b][1][c] + nf[b][2][c] + nf[b][3][c] + nf[b][4][c]
                + b1[c] + b2[c] + b3[c] + b4[c] + b5[c];
        zsh[b][c] = 0.2f * s;
    }
    __syncthreads();

    // ---- phase 3: fn = z @ gcn_w + gcn_b ----
    if (tid < BATCH * CMID) {
        int b = tid >> 4, c = tid & 15;
        float s = gcn_b[c];
        for (int k = 0; k < CMID; ++k) s += zsh[b][k] * gcn_w[k * CMID + c];
        fnsh[b][c] = s;
    }
    __syncthreads();

    // ---- phase 4: M, beta ----
    {
        int b = tid >> 5, co = tid & 31;
        float bt = fusion_b[co];
        for (int c = 0; c < CMID; ++c) {
            float K = swsh[0] * b1[c] + swsh[1] * b2[c] + swsh[2] * b3[c] + swsh[3] * b4[c]
                    + swsh[4] * (nf[b][4][c] + b5[c]);       // f5 value (constant map)
            float m = fusion_w[co * CMID + c] * fnsh[b][c];
            g_M[(b * COUT + co) * CMID + c] = m;
            bt += m * K;
        }
        g_beta[b * COUT + co] = bt;
    }

    // ---- phase 5: folded 25-tap stage-1 weights, scaled by softmax weights ----
    for (int idx = tid; idx < CIN * NTAPS * CMID; idx += 256) {
        int ci = idx / (NTAPS * CMID);
        int r = idx - ci * (NTAPS * CMID);
        int t = r >> 4;
        int c = r & 15;
        int dyo, dx;
        if (t < 9)       { int g = t / 3; dyo = g - 3; dx = (t - g * 3 - 1) * (3 - g); }
        else if (t < 16) { dyo = 0; dx = t - 12; }
        else             { int g = (t - 16) / 3; dyo = g + 1; dx = ((t - 16) - g * 3 - 1) * (g + 1); }
        float v = 0.f;
        if (dyo == 0 && dx == 0) v += swsh[0] * w1[c * CIN + ci];
        for (int d = 1; d <= 3; ++d) {
            const float* wd = (d == 1) ? w2 : (d == 2) ? w3 : w4;
            bool iny = (dyo == 0 || dyo == d || dyo == -d);
            bool inx = (dx  == 0 || dx  == d || dx  == -d);
            if (iny && inx) {
                int ky = dyo / d + 1, kx = dx / d + 1;
                v += swsh[d] * wd[(c * CIN + ci) * 9 + ky * 3 + kx];
            }
        }
        g_W25[idx] = v;
    }
}

// ============================================================
// Kernel C: fused 25-tap conv (32->16) + pointwise (16->32) per batch.
// Tile: 128x8 pixels, 256 threads, 4 px/thread, halo 3.
// Weights come from __constant__ (LDCU/uniform path); x tile is
// register-prefetch double-buffered so LDG latency overlaps compute.
// ============================================================
#define TX 128
#define TY 8
#define XS_STRIDE 136   // TX + 6 halo + 2 pad (keeps float4 reads in-bounds)
#define XS_ROWS   14    // TY + 6
#define NXS (XS_ROWS * XS_STRIDE)                  // 1904
#define SMEM_M    (COUT * CMID)                    // 512
#define SMEM_FLOATS (SMEM_M + COUT + NXS)          // 2448

__global__ void __launch_bounds__(256, 2)
main_kernel(const float* __restrict__ x, float* __restrict__ y) {
    extern __shared__ float smem[];
    float* Msh    = smem;                       // 512
    float* betash = Msh + SMEM_M;               // 32
    float* xs     = betash + COUT;              // 14 x 136

    const int b  = blockIdx.z;
    const int h0 = blockIdx.y * TY;
    const int w0 = blockIdx.x * TX;
    const int tid = threadIdx.x;
    const int ty  = tid >> 5;      // 0..7
    const int tx4 = tid & 31;      // 0..31; pixels w0 + tx4*4 + {0..3}

    for (int i = tid; i < SMEM_M; i += 256) Msh[i] = g_M[b * SMEM_M + i];
    if (tid < COUT) betash[tid] = g_beta[b * COUT + tid];

    // acc pairs over adjacent mid-channels: accp[cp][p] holds (c=2cp, c=2cp+1) for pixel p
    ull accp[CMID / 2][4];
#pragma unroll
    for (int cp = 0; cp < CMID / 2; ++cp)
#pragma unroll
        for (int p = 0; p < 4; ++p) accp[cp][p] = 0ull;

    // ---- initial fill of x tile for ci = 0 ----
    {
        const float* xp = x + (size_t)(b * CIN) * PLANE;
#pragma unroll
        for (int it = 0; it < 8; ++it) {
            int i = tid + it * 256;
            if (i < NXS) {
                int r  = i / XS_STRIDE;
                int cc = i - r * XS_STRIDE;
                int h = h0 - 3 + r;
                int w = w0 - 3 + cc;
                float v = 0.f;
                if ((unsigned)h < HH && (unsigned)w < WW) v = xp[h * WW + w];
                xs[i] = v;
            }
        }
    }

#pragma unroll 1
    for (int ci = 0; ci < CIN; ++ci) {
        __syncthreads();   // xs (stores from prev iter / initial fill) visible

        // prefetch next ci's tile into registers; LDGs overlap the compute below
        float pf[8];
        if (ci + 1 < CIN) {
            const float* xq = x + (size_t)(b * CIN + ci + 1) * PLANE;
#pragma unroll
            for (int it = 0; it < 8; ++it) {
                int i = tid + it * 256;
                float v = 0.f;
                if (i < NXS) {
                    int r  = i / XS_STRIDE;
                    int cc = i - r * XS_STRIDE;
                    int h = h0 - 3 + r;
                    int w = w0 - 3 + cc;
                    if ((unsigned)h < HH && (unsigned)w < WW) v = xq[h * WW + w];
                }
                pf[it] = v;
            }
        }

        const ull* wci = cW25u + ci * (NTAPS * CMID / 2);
        const float* xbase = xs + ty * XS_STRIDE + tx4 * 4;

#pragma unroll
        for (int dyi = 0; dyi < 7; ++dyi) {
            const float4 a0 = *(const float4*)(xbase + dyi * XS_STRIDE);
            const float4 a1 = *(const float4*)(xbase + dyi * XS_STRIDE + 4);
            const float4 a2 = *(const float4*)(xbase + dyi * XS_STRIDE + 8);
            const float xr[10] = {a0.x, a0.y, a0.z, a0.w, a1.x, a1.y, a1.z, a1.w,
                                  a2.x, a2.y};
            ull xb[10];  // broadcast pairs {x,x}
#pragma unroll
            for (int k = 0; k < 10; ++k) PACKF2(xb[k], xr[k], xr[k]);

            const int aD = (dyi < 3) ? (3 - dyi) : (dyi - 3);
            const int nt = (dyi == 3) ? 7 : 3;
            const int tb = (dyi < 3) ? 3 * dyi : ((dyi == 3) ? 9 : 16 + 3 * (dyi - 4));
#pragma unroll
            for (int k = 0; k < nt; ++k) {
                const int dx = (dyi == 3) ? (k - 3) : ((k - 1) * aD);
                const ull* wt = wci + (tb + k) * (CMID / 2);
#pragma unroll
                for (int cp = 0; cp < CMID / 2; ++cp) {
                    const ull w2v = wt[cp];   // ld.const.u64, warp-uniform -> LDCU/UR
                    FFMA2(accp[cp][0], w2v, xb[3 + dx]);
                    FFMA2(accp[cp][1], w2v, xb[4 + dx]);
                    FFMA2(accp[cp][2], w2v, xb[5 + dx]);
                    FFMA2(accp[cp][3], w2v, xb[6 + dx]);
                }
            }
        }

        __syncthreads();   // everyone done reading xs
        if (ci + 1 < CIN) {
#pragma unroll
            for (int it = 0; it < 8; ++it) {
                int i = tid + it * 256;
                if (i < NXS) xs[i] = pf[it];
            }
        }
    }

    // ---- epilogue: y[co] = sum_c M[co][c]*acc[c] + beta[co], packed over c pairs ----
    const int h = h0 + ty;
    float* yp = y + ((size_t)(b * COUT) * HH + h) * WW + w0 + tx4 * 4;
#pragma unroll 1
    for (int co = 0; co < COUT; ++co) {
        const ull* m64 = (const ull*)(Msh + co * CMID);
        ull o[4] = {0ull, 0ull, 0ull, 0ull};
#pragma unroll
        for (int cp = 0; cp < CMID / 2; ++cp) {
            const ull mv = m64[cp];
            FFMA2(o[0], mv, accp[cp][0]);
            FFMA2(o[1], mv, accp[cp][1]);
            FFMA2(o[2], mv, accp[cp][2]);
            FFMA2(o[3], mv, accp[cp][3]);
        }
        const float bt = betash[co];
        float4 ov;
        {
            float lo, hi;
            UNPACKF2(lo, hi, o[0]); ov.x = lo + hi + bt;
            UNPACKF2(lo, hi, o[1]); ov.y = lo + hi + bt;
            UNPACKF2(lo, hi, o[2]); ov.z = lo + hi + bt;
            UNPACKF2(lo, hi, o[3]); ov.w = lo + hi + bt;
        }
        *(float4*)(yp + (size_t)co * PLANE) = ov;
    }
}

// ============================================================
extern "C" void kernel_launch(void* const* d_in, const int* in_sizes, int n_in,
                              void* d_out, int out_size) {
    const float* x        = (const float*)d_in[0];
    const float* w1       = (const float*)d_in[1];
    const float* b1       = (const float*)d_in[2];
    const float* w2       = (const float*)d_in[3];
    const float* b2       = (const float*)d_in[4];
    const float* w3       = (const float*)d_in[5];
    const float* b3       = (const float*)d_in[6];
    const float* w4       = (const float*)d_in[7];
    const float* b4       = (const float*)d_in[8];
    const float* w5       = (const float*)d_in[9];
    const float* b5       = (const float*)d_in[10];
    const float* gcn_w    = (const float*)d_in[11];
    const float* gcn_b    = (const float*)d_in[12];
    const float* attn     = (const float*)d_in[13];
    const float* fusion_w = (const float*)d_in[14];
    const float* fusion_b = (const float*)d_in[15];
    float* y = (float*)d_out;

    cudaFuncSetAttribute(main_kernel, cudaFuncAttributeMaxDynamicSharedMemorySize,
                         SMEM_FLOATS * 4);

    stats_kernel<<<NPLANES * NSLICE, 256>>>(x);
    prep_kernel<<<1, 256>>>(x, w1, b1, w2, b2, w3, b3, w4, b4, w5, b5,
                            gcn_w, gcn_b, attn, fusion_w, fusion_b);

    // bridge folded weights into constant memory (graph-capturable D2D copy)
    void* w25_dev = nullptr;
    cudaGetSymbolAddress(&w25_dev, g_W25);
    cudaMemcpyToSymbolAsync(cW25u, w25_dev, CIN * NTAPS * CMID * sizeof(float), 0,
                            cudaMemcpyDeviceToDevice, 0);

    dim3 grid(WW / TX, HH / TY, BATCH);
    main_kernel<<<grid, 256, SMEM_FLOATS * 4>>>(x, y);
}

// round 17
// speedup vs baseline: 1.2467x; 1.0638x over previous
#include <cuda_runtime.h>
#include <cuda_bf16.h>
#include <math.h>
#include <cstdint>
#include <cstring>

#define BATCH 8
#define CIN 32
#define CMID 16
#define COUT 32
#define HH 384
#define WW 384
#define PLANE (HH*WW)
#define NPLANES 256
#define NSLICE 8
#define SLICE_ROWS 48
#define SLICE_F4 (SLICE_ROWS*WW/4)
#define NTAPS 25
#define NKS 50                    // 50 k-steps of 16 (K = 800)

typedef unsigned long long ull;

// packed f32x2 helpers (proven in R8)
#define FFMA2(acc, a, b) asm("fma.rn.f32x2 %0, %1, %2, %0;" : "+l"(acc) : "l"(a), "l"(b))
#define PACKF2(out, lo, hi) asm("mov.b64 %0, {%1, %2};" : "=l"(out) : "f"(lo), "f"(hi))
#define UNPACKF2(lo, hi, in) asm("mov.b64 {%0, %1}, %2;" : "=f"(lo), "=f"(hi) : "l"(in))
#define LDS32(r, a)  asm volatile("ld.shared.b32 %0, [%1];" : "=r"(r) : "r"(a))
#define LDS128F(f0,f1,f2,f3,a) asm volatile("ld.shared.v4.f32 {%0,%1,%2,%3}, [%4];" : "=f"(f0),"=f"(f1),"=f"(f2),"=f"(f3) : "r"(a))
#define LDS128U(r0,r1,r2,r3,a) asm volatile("ld.shared.v4.u32 {%0,%1,%2,%3}, [%4];" : "=r"(r0),"=r"(r1),"=r"(r2),"=r"(r3) : "r"(a))
#define STS32(a, v)  asm volatile("st.shared.b32 [%0], %1;" :: "r"(a), "r"(v) : "memory")
#define STS64F(a, v0, v1) asm volatile("st.shared.v2.f32 [%0], {%1,%2};" :: "r"(a), "f"(v0), "f"(v1) : "memory")

// mma.sync m16n8k16 bf16 -> f32 (baseline PTX, works on sm_103 target)
__device__ __forceinline__ void mma16816(float* d, const uint32_t* a, const uint32_t* b) {
    asm volatile("mma.sync.aligned.m16n8k16.row.col.f32.bf16.bf16.f32 "
                 "{%0,%1,%2,%3}, {%4,%5,%6,%7}, {%8,%9}, {%0,%1,%2,%3};"
                 : "+f"(d[0]), "+f"(d[1]), "+f"(d[2]), "+f"(d[3])
                 : "r"(a[0]), "r"(a[1]), "r"(a[2]), "r"(a[3]), "r"(b[0]), "r"(b[1]));
}

__device__ __forceinline__ uint32_t smem_to_u32(const void* p) {
    uint32_t a;
    asm("{ .reg .u64 t; cvta.to.shared.u64 t, %1; cvt.u32.u64 %0, t; }" : "=r"(a) : "l"(p));
    return a;
}

// ---- device scratch ----
__device__ float g_part[NPLANES*NSLICE*13];
__device__ float g_M[BATCH*COUT*CMID];
__device__ float g_beta[BATCH*COUT];
__device__ __align__(16) uint32_t g_Bf[NKS*32*8];   // per-(kstep,lane): hi frag uint4 + lo frag uint4 = 51200B
__device__ ull g_Mp[BATCH*16*16];                   // packed stage-2 weights [b][c][copair]

// tap tables: (dy,dx) of the 25 folded taps (K order: tap-major, ci-minor)
__constant__ int DYT[NTAPS] = {0,0,0,0,0,0,0, -1,-1,-1, 1,1,1, -2,-2,-2, 2,2,2, -3,-3,-3, 3,3,3};
__constant__ int DXT[NTAPS] = {-3,-2,-1,0,1,2,3, -1,0,1, -1,0,1, -2,0,2, -2,0,2, -3,0,3, -3,0,3};

__device__ __forceinline__ uint16_t bfb(float f) {
    __nv_bfloat16 h = __float2bfloat16(f);
    uint16_t u; memcpy(&u, &h, 2); return u;
}
__device__ __forceinline__ float bf2f(uint16_t u) {
    __nv_bfloat16 h; memcpy(&h, &u, 2); return __bfloat162float(h);
}

// ============================================================
// Kernel A: per-slice stats (unchanged; proven 29us)
// ============================================================
__device__ __forceinline__ float warp_red(float v) {
#pragma unroll
    for (int o = 16; o > 0; o >>= 1) v += __shfl_xor_sync(0xffffffffu, v, o);
    return v;
}
__global__ void stats_kernel(const float* __restrict__ x) {
    int blk = blockIdx.x, plane = blk >> 3, slice = blk & 7;
    const float4* xp = (const float4*)(x + (size_t)plane * PLANE + (size_t)slice * SLICE_ROWS * WW);
    int tid = threadIdx.x;
    const bool bnd = (slice == 0 || slice == 7);
    float T=0,c0=0,c1=0,c2=0,c3=0,c4=0,c5=0,r0=0,r1=0,r2=0;
#pragma unroll
    for (int it = 0; it < SLICE_F4/256; ++it) {
        int i = tid + it*256;
        float4 v = xp[i];
        float s4 = v.x+v.y+v.z+v.w;
        T += s4;
        int cq = i % 96;
        if (cq == 0)  { c0 += v.x; c1 += v.y; c2 += v.z; }
        if (cq == 95) { c3 += v.y; c4 += v.z; c5 += v.w; }
        if (bnd) {
            int lr = i/96, key = (slice==0) ? lr : (47-lr);
            if (key==0) r0+=s4; else if (key==1) r1+=s4; else if (key==2) r2+=s4;
        }
    }
    __shared__ float s13[13];
    if (tid < 13) s13[tid] = 0.f;
    __syncthreads();
    T=warp_red(T); c0=warp_red(c0); c1=warp_red(c1); c2=warp_red(c2);
    c3=warp_red(c3); c4=warp_red(c4); c5=warp_red(c5);
    if (bnd) { r0=warp_red(r0); r1=warp_red(r1); r2=warp_red(r2); }
    if ((tid & 31) == 0) {
        atomicAdd(&s13[0],T);
        atomicAdd(&s13[7],c0); atomicAdd(&s13[8],c1); atomicAdd(&s13[9],c2);
        atomicAdd(&s13[10],c3); atomicAdd(&s13[11],c4); atomicAdd(&s13[12],c5);
        if (bnd) {
            if (slice==0) { atomicAdd(&s13[1],r0); atomicAdd(&s13[2],r1); atomicAdd(&s13[3],r2); }
            else          { atomicAdd(&s13[6],r0); atomicAdd(&s13[5],r1); atomicAdd(&s13[4],r2); }
        }
    }
    __syncthreads();
    if (tid < 13) g_part[blk*13 + tid] = s13[tid];
}

__device__ __forceinline__ float ps_fun(const float* __restrict__ xp, const float* __restrict__ st,
                                        int dy, int dx) {
    float s = st[0];
    if (dy>0)      for (int r=0; r<dy;  ++r) s -= st[1+r];
    else if (dy<0) for (int r=0; r<-dy; ++r) s -= st[6-r];
    if (dx>0)      for (int c=0; c<dx;  ++c) s -= st[7+c];
    else if (dx<0) for (int c=0; c<-dx; ++c) s -= st[12-c];
    if (dy!=0 && dx!=0) {
        int r0=(dy>0)?0:HH+dy, r1=(dy>0)?dy-1:HH-1;
        int cc0=(dx>0)?0:WW+dx, cc1=(dx>0)?dx-1:WW-1;
        for (int r=r0; r<=r1; ++r) for (int c=cc0; c<=cc1; ++c) s += xp[r*WW+c];
    }
    return s;
}

// folded stage-1 weight for (tap, ci, cmid)
__device__ __forceinline__ float wfold(int tap, int ci, int c, const float* sw,
                                       const float* w1, const float* w2,
                                       const float* w3, const float* w4) {
    int dy = DYT[tap], dx = DXT[tap];
    float v = 0.f;
    if (dy==0 && dx==0) v += sw[0]*w1[c*CIN+ci];
    for (int d=1; d<=3; ++d) {
        const float* wd = (d==1)?w2:(d==2)?w3:w4;
        bool iny = (dy==0||dy==d||dy==-d);
        bool inx = (dx==0||dx==d||dx==-d);
        if (iny && inx)
            v += sw[d]*wd[(c*CIN+ci)*9 + (dy/d+1)*3 + (dx/d+1)];
    }
    return v;
}

// ============================================================
// Kernel B: node feats -> M/beta/Mp; folded weights -> mma B fragments (hi/lo)
// ============================================================
__global__ void prep_kernel(const float* __restrict__ x,
                            const float* __restrict__ w1, const float* __restrict__ b1,
                            const float* __restrict__ w2, const float* __restrict__ b2,
                            const float* __restrict__ w3, const float* __restrict__ b3,
                            const float* __restrict__ w4, const float* __restrict__ b4,
                            const float* __restrict__ w5, const float* __restrict__ b5,
                            const float* __restrict__ gcn_w, const float* __restrict__ gcn_b,
                            const float* __restrict__ attn,
                            const float* __restrict__ fusion_w, const float* __restrict__ fusion_b) {
    __shared__ float nf[BATCH][5][CMID];
    __shared__ float zsh[BATCH][CMID];
    __shared__ float fnsh[BATCH][CMID];
    __shared__ float swsh[5];
    int tid = threadIdx.x;
    for (int i = tid; i < BATCH*5*CMID; i += 256) ((float*)nf)[i] = 0.f;
    if (tid == 0) {
        float m = attn[0];
        for (int i=1;i<5;++i) m = fmaxf(m, attn[i]);
        float e[5], s = 0.f;
        for (int i=0;i<5;++i) { e[i] = expf(attn[i]-m); s += e[i]; }
        for (int i=0;i<5;++i) swsh[i] = e[i]/s;
    }
    __syncthreads();
    { // exact per-branch node features
        int b = tid >> 5, ci = tid & 31, plane = b*CIN + ci;
        const float* xp = x + (size_t)plane * PLANE;
        float st[13];
        for (int i=0;i<13;++i) {
            float s=0.f;
            for (int sl=0; sl<NSLICE; ++sl) s += g_part[(plane*NSLICE+sl)*13 + i];
            st[i]=s;
        }
        const float invHW = 1.0f/(float)PLANE;
        float xm = st[0]*invHW;
        for (int c=0;c<CMID;++c) {
            atomicAdd(&nf[b][0][c], w1[c*CIN+ci]*xm);
            atomicAdd(&nf[b][4][c], w5[c*CIN+ci]*xm);
        }
        for (int d=1;d<=3;++d) {
            float ps[9];
            for (int ky=0;ky<3;++ky) for (int kx=0;kx<3;++kx)
                ps[ky*3+kx] = ps_fun(xp, st, d*(ky-1), d*(kx-1))*invHW;
            const float* wd = (d==1)?w2:(d==2)?w3:w4;
            for (int c=0;c<CMID;++c) {
                float p=0.f;
                for (int j=0;j<9;++j) p += wd[(c*CIN+ci)*9+j]*ps[j];
                atomicAdd(&nf[b][d][c], p);
            }
        }
    }
    __syncthreads();
    if (tid < BATCH*CMID) {
        int b=tid>>4, c=tid&15;
        float s = nf[b][0][c]+nf[b][1][c]+nf[b][2][c]+nf[b][3][c]+nf[b][4][c]
                + b1[c]+b2[c]+b3[c]+b4[c]+b5[c];
        zsh[b][c] = 0.2f*s;
    }
    __syncthreads();
    if (tid < BATCH*CMID) {
        int b=tid>>4, c=tid&15;
        float s = gcn_b[c];
        for (int k=0;k<CMID;++k) s += zsh[b][k]*gcn_w[k*CMID+c];
        fnsh[b][c] = s;
    }
    __syncthreads();
    { // M, beta
        int b = tid>>5, co = tid&31;
        float bt = fusion_b[co];
        for (int c=0;c<CMID;++c) {
            float K = swsh[0]*b1[c]+swsh[1]*b2[c]+swsh[2]*b3[c]+swsh[3]*b4[c]
                    + swsh[4]*(nf[b][4][c]+b5[c]);
            float m = fusion_w[co*CMID+c]*fnsh[b][c];
            g_M[(b*COUT+co)*CMID+c] = m;
            bt += m*K;
        }
        g_beta[b*COUT+co] = bt;
    }
    __syncthreads();
    // packed stage-2 weights: Mp[b][c][cp2] = {M[2cp2][c], M[2cp2+1][c]}
    for (int idx = tid; idx < BATCH*16*16; idx += 256) {
        int b = idx >> 8, c = (idx >> 4) & 15, cp2 = idx & 15;
        float fe = g_M[(b*COUT + 2*cp2)*CMID + c];
        float fo = g_M[(b*COUT + 2*cp2 + 1)*CMID + c];
        ull u = ((ull)__float_as_uint(fo) << 32) | (ull)__float_as_uint(fe);
        g_Mp[idx] = u;
    }
    // mma B fragments (hi/lo), fragment-ordered: [ks][lane]{hi uint4 | lo uint4}
    for (int idx = tid; idx < NKS*32; idx += 256) {
        int ks = idx >> 5, lane = idx & 31;
        int g = lane >> 2, t4 = lane & 3;
        int tap = ks >> 1, ch = ks & 1;
        uint32_t hi[4], lo[4];
#pragma unroll
        for (int n = 0; n < 2; ++n) {
#pragma unroll
            for (int bb = 0; bb < 2; ++bb) {
                int k0 = 2*t4 + bb*8;            // k rows k0, k0+1
                int c  = n*8 + g;
                float v0 = wfold(tap, ch*16 + k0,     c, swsh, w1, w2, w3, w4);
                float v1 = wfold(tap, ch*16 + k0 + 1, c, swsh, w1, w2, w3, w4);
                uint16_t h0 = bfb(v0), h1 = bfb(v1);
                float r0 = v0 - bf2f(h0), r1 = v1 - bf2f(h1);
                uint16_t l0 = bfb(r0), l1 = bfb(r1);
                hi[n*2+bb] = (uint32_t)h0 | ((uint32_t)h1 << 16);
                lo[n*2+bb] = (uint32_t)l0 | ((uint32_t)l1 << 16);
            }
        }
        uint32_t* dst = g_Bf + idx*8;
        dst[0]=hi[0]; dst[1]=hi[1]; dst[2]=hi[2]; dst[3]=hi[3];
        dst[4]=lo[0]; dst[5]=lo[1]; dst[6]=lo[2]; dst[7]=lo[3];
    }
}

// ============================================================
// Kernel C: mma.sync implicit conv. 144 CTAs (3 wtiles x 6 rowchunks x 8 b).
// smem: 8-row ring [cp16][px134] bf16-pair hi/lo + B frags + staging.
// ============================================================
#define CP_PITCH 544                 // 134*4 + 8 pad
#define RING_HL  (16*CP_PITCH)       // 8704 (hi region; lo at +8704)
#define RING_SLOT (2*RING_HL)        // 17408
#define SM_RING 0                    // 8 slots = 139264
#define SM_BF   (8*RING_SLOT)        // 139264, size 51200
#define SM_STAG (SM_BF + 51200)      // 190464, 8 warps x 1280
#define SM_TOTAL (SM_STAG + 8*1280)  // 200704

__device__ __forceinline__ void produce_row(uint32_t sb, const float* __restrict__ x,
                                            int b, int w0, int srow, int tid) {
    int cp = tid >> 4, w16 = tid & 15;
    int slot = (srow + 1024) & 7;
    const float* p0 = x + ((size_t)(b*CIN) + 2*cp)*PLANE + (size_t)((unsigned)srow < HH ? srow : 0)*WW;
    const float* p1 = p0 + PLANE;
    bool rok = ((unsigned)srow < HH);
    uint32_t base = sb + SM_RING + slot*RING_SLOT + cp*CP_PITCH;
#pragma unroll
    for (int j = 0; j < 9; ++j) {
        int px = w16 + 16*j;
        if (px < 134) {
            int gw = w0 - 3 + px;
            bool ok = rok && (unsigned)gw < WW;
            float v0 = ok ? p0[gw] : 0.f;
            float v1 = ok ? p1[gw] : 0.f;
            uint16_t h0 = bfb(v0), h1 = bfb(v1);
            uint32_t wh = (uint32_t)h0 | ((uint32_t)h1 << 16);
            uint16_t l0 = bfb(v0 - bf2f(h0)), l1 = bfb(v1 - bf2f(h1));
            uint32_t wl = (uint32_t)l0 | ((uint32_t)l1 << 16);
            STS32(base + px*4, wh);
            STS32(base + RING_HL + px*4, wl);
        }
    }
}

__global__ void __launch_bounds__(256, 1)
main_kernel(const float* __restrict__ x, float* __restrict__ y) {
    extern __shared__ unsigned char smem[];
    const uint32_t sb = smem_to_u32(smem);
    const int tid = threadIdx.x;
    const int wid = tid >> 5, lane = tid & 31;
    const int g = lane >> 2, t4 = lane & 3;
    const int b  = blockIdx.z;
    const int w0 = blockIdx.x * 128;
    const int r0 = blockIdx.y * 64;

    // copy B fragments into smem
    { const uint4* s = (const uint4*)g_Bf;
      uint4* d = (uint4*)(smem + SM_BF);
      for (int i = tid; i < 3200; i += 256) d[i] = s[i]; }

    // stage-2 per-thread constants
    const int co2 = lane & 15, pxoct = lane >> 4;
    ull mp[16];
#pragma unroll
    for (int c = 0; c < 16; ++c) mp[c] = g_Mp[(b*16 + c)*16 + co2];
    ull beta2;
    { float be = g_beta[b*32 + 2*co2], bo = g_beta[b*32 + 2*co2 + 1];
      PACKF2(beta2, be, bo); }

    // preload ring rows r0-3 .. r0+3
    for (int rr = 0; rr < 7; ++rr) produce_row(sb, x, b, w0, r0 - 3 + rr, tid);
    __syncthreads();

    const int cp = tid >> 4, w16 = tid & 15;
    const int pxb = wid*16 + g + 3;     // ring px of A row g (before dx)

    for (int k = 0; k < 64; ++k) {
        const int h = r0 + k;
        // ---- prefetch next row into registers (overlaps mma below) ----
        const int srow = h + 4;
        float v0r[9], v1r[9];
        {
            const float* p0 = x + ((size_t)(b*CIN) + 2*cp)*PLANE + (size_t)(srow < HH ? srow : 0)*WW;
            const float* p1 = p0 + PLANE;
            bool rok = (srow < HH);
#pragma unroll
            for (int j = 0; j < 9; ++j) {
                int px = w16 + 16*j;
                int gw = w0 - 3 + px;
                bool ok = rok && px < 134 && (unsigned)gw < WW;
                v0r[j] = ok ? p0[gw] : 0.f;
                v1r[j] = ok ? p1[gw] : 0.f;
            }
        }

        // ---- mma main loop: 50 ksteps ----
        float acc0[4] = {0.f,0.f,0.f,0.f};   // cmid 0..7
        float acc1[4] = {0.f,0.f,0.f,0.f};   // cmid 8..15
#pragma unroll 1
        for (int ks = 0; ks < NKS; ++ks) {
            const int tap = ks >> 1, ch = ks & 1;
            const int slot = (h + DYT[tap] + 1024) & 7;
            const int px = pxb + DXT[tap];
            const uint32_t ab = sb + SM_RING + slot*RING_SLOT + (ch*8 + t4)*CP_PITCH + px*4;
            uint32_t ah[4], al[4];
            LDS32(ah[0], ab);                  // (g,   k 2t4..)
            LDS32(ah[1], ab + 32);             // (g+8, k 2t4..)
            LDS32(ah[2], ab + 4*CP_PITCH);     // (g,   k 2t4+8..)
            LDS32(ah[3], ab + 4*CP_PITCH + 32);
            LDS32(al[0], ab + RING_HL);
            LDS32(al[1], ab + RING_HL + 32);
            LDS32(al[2], ab + RING_HL + 4*CP_PITCH);
            LDS32(al[3], ab + RING_HL + 4*CP_PITCH + 32);
            uint32_t bh[4], bl[4];
            const uint32_t baddr = sb + SM_BF + (ks*32 + lane)*32;
            LDS128U(bh[0],bh[1],bh[2],bh[3], baddr);
            LDS128U(bl[0],bl[1],bl[2],bl[3], baddr + 16);
            mma16816(acc0, ah, bh);
            mma16816(acc0, al, bh);
            mma16816(acc0, ah, bl);
            mma16816(acc1, ah, bh + 2);
            mma16816(acc1, al, bh + 2);
            mma16816(acc1, ah, bl + 2);
        }

        // ---- stage acc (c-fragment layout) to smem ----
        const uint32_t stg = sb + SM_STAG + wid*1280;
        STS64F(stg + g*80      + (2*t4)*4,     acc0[0], acc0[1]);
        STS64F(stg + (g+8)*80  + (2*t4)*4,     acc0[2], acc0[3]);
        STS64F(stg + g*80      + (8+2*t4)*4,   acc1[0], acc1[1]);
        STS64F(stg + (g+8)*80  + (8+2*t4)*4,   acc1[2], acc1[3]);
        __syncwarp();

        // ---- stage-2 pointwise (16 -> 32) in fp32x2 ----
        ull a2[8];
#pragma unroll
        for (int i = 0; i < 8; ++i) a2[i] = beta2;
#pragma unroll
        for (int pxi = 0; pxi < 8; ++pxi) {
            const uint32_t sa = stg + (pxoct*8 + pxi)*80;
#pragma unroll
            for (int cq = 0; cq < 4; ++cq) {
                float f0,f1,f2,f3;
                LDS128F(f0,f1,f2,f3, sa + cq*16);
                ull x0,x1,x2,x3;
                PACKF2(x0,f0,f0); PACKF2(x1,f1,f1); PACKF2(x2,f2,f2); PACKF2(x3,f3,f3);
                FFMA2(a2[pxi], mp[cq*4+0], x0);
                FFMA2(a2[pxi], mp[cq*4+1], x1);
                FFMA2(a2[pxi], mp[cq*4+2], x2);
                FFMA2(a2[pxi], mp[cq*4+3], x3);
            }
        }
        // unpack + store: even co plane gets lows, odd co plane highs
        {
            float lov[8], hiv[8];
#pragma unroll
            for (int i = 0; i < 8; ++i) UNPACKF2(lov[i], hiv[i], a2[i]);
            const int wg = w0 + wid*16 + pxoct*8;
            float* ye = y + ((size_t)(b*COUT + 2*co2)*HH + h)*WW + wg;
            float* yo = ye + (size_t)PLANE;
            *(float4*)ye       = make_float4(lov[0],lov[1],lov[2],lov[3]);
            *(float4*)(ye + 4) = make_float4(lov[4],lov[5],lov[6],lov[7]);
            *(float4*)yo       = make_float4(hiv[0],hiv[1],hiv[2],hiv[3]);
            *(float4*)(yo + 4) = make_float4(hiv[4],hiv[5],hiv[6],hiv[7]);
        }
        __syncwarp();

        // ---- write prefetched row into ring slot (h+4)&7 ----
        {
            const int slot = (srow + 1024) & 7;
            const uint32_t base = sb + SM_RING + slot*RING_SLOT + cp*CP_PITCH;
#pragma unroll
            for (int j = 0; j < 9; ++j) {
                int px = w16 + 16*j;
                if (px < 134) {
                    uint16_t h0 = bfb(v0r[j]), h1 = bfb(v1r[j]);
                    uint32_t wh = (uint32_t)h0 | ((uint32_t)h1 << 16);
                    uint16_t l0 = bfb(v0r[j] - bf2f(h0)), l1 = bfb(v1r[j] - bf2f(h1));
                    uint32_t wl = (uint32_t)l0 | ((uint32_t)l1 << 16);
                    STS32(base + px*4, wh);
                    STS32(base + RING_HL + px*4, wl);
                }
            }
        }
        __syncthreads();
    }
}

// ============================================================
extern "C" void kernel_launch(void* const* d_in, const int* in_sizes, int n_in,
                              void* d_out, int out_size) {
    const float* x        = (const float*)d_in[0];
    const float* w1       = (const float*)d_in[1];
    const float* b1       = (const float*)d_in[2];
    const float* w2       = (const float*)d_in[3];
    const float* b2       = (const float*)d_in[4];
    const float* w3       = (const float*)d_in[5];
    const float* b3       = (const float*)d_in[6];
    const float* w4       = (const float*)d_in[7];
    const float* b4       = (const float*)d_in[8];
    const float* w5       = (const float*)d_in[9];
    const float* b5       = (const float*)d_in[10];
    const float* gcn_w    = (const float*)d_in[11];
    const float* gcn_b    = (const float*)d_in[12];
    const float* attn     = (const float*)d_in[13];
    const float* fusion_w = (const float*)d_in[14];
    const float* fusion_b = (const float*)d_in[15];
    float* y = (float*)d_out;

    static_assert(SM_TOTAL < 227*1024, "smem");
    cudaFuncSetAttribute(main_kernel, cudaFuncAttributeMaxDynamicSharedMemorySize, SM_TOTAL);

    stats_kernel<<<NPLANES*NSLICE, 256>>>(x);
    prep_kernel<<<1, 256>>>(x, w1, b1, w2, b2, w3, b3, w4, b4, w5, b5,
                            gcn_w, gcn_b, attn, fusion_w, fusion_b);
    dim3 grid(3, 6, BATCH);
    main_kernel<<<grid, 256, SM_TOTAL>>>(x, y);
}